// round 1
// baseline (speedup 1.0000x reference)
#include <cuda_runtime.h>
#include <math.h>

#define B_  4
#define S_  1024
#define D_  1024
#define H_  16
#define HD_ 64

// ---- scratch (no cudaMalloc allowed) ----
__device__ float g_Q[B_*H_*S_*HD_];     // [B,H,S,HD]
__device__ float g_K[B_*H_*S_*HD_];
__device__ float g_V[B_*H_*S_*HD_];
__device__ float g_attn[B_*S_*D_];      // [B,S,D] (heads re-interleaved)
__device__ float g_proj[B_*S_*D_];      // after Wo projection

// ============================================================
// 128x128x16 SGEMM, 256 threads, 8x8 per thread.
// QKV: one launch, blockIdx.z selects which projection.
// Epilogue writes [B,H,S,HD] layout.
// ============================================================
__global__ __launch_bounds__(256) void qkv_proj_kernel(
    const float* __restrict__ q_in, const float* __restrict__ k_in,
    const float* __restrict__ v_in,
    const float* __restrict__ Wq, const float* __restrict__ bq,
    const float* __restrict__ Wk, const float* __restrict__ bk,
    const float* __restrict__ Wv, const float* __restrict__ bv)
{
    const int z = blockIdx.z;
    const float* __restrict__ X    = (z == 0) ? q_in : (z == 1) ? k_in : v_in;
    const float* __restrict__ W    = (z == 0) ? Wq   : (z == 1) ? Wk   : Wv;
    const float* __restrict__ bias = (z == 0) ? bq   : (z == 1) ? bk   : bv;
    float* __restrict__ outp       = (z == 0) ? g_Q  : (z == 1) ? g_K  : g_V;

    __shared__ float As[16][128];   // A transposed: As[k][m]
    __shared__ float Bs[16][128];   // Bs[k][n]

    const int tid  = threadIdx.x;
    const int tx   = tid & 15;
    const int ty   = tid >> 4;
    const int row0 = blockIdx.y * 128;
    const int col0 = blockIdx.x * 128;

    const int ar = tid >> 2;          // 0..63
    const int ac = (tid & 3) << 2;    // 0,4,8,12
    const int br = tid >> 5;          // 0..7
    const int bc = (tid & 31) << 2;   // 0..124

    float acc[8][8];
    #pragma unroll
    for (int i = 0; i < 8; i++)
        #pragma unroll
        for (int j = 0; j < 8; j++) acc[i][j] = 0.f;

    for (int k0 = 0; k0 < D_; k0 += 16) {
        #pragma unroll
        for (int i = 0; i < 2; i++) {
            float4 a = *(const float4*)(X + (size_t)(row0 + ar + i*64) * D_ + k0 + ac);
            As[ac+0][ar + i*64] = a.x;
            As[ac+1][ar + i*64] = a.y;
            As[ac+2][ar + i*64] = a.z;
            As[ac+3][ar + i*64] = a.w;
        }
        #pragma unroll
        for (int i = 0; i < 2; i++) {
            *(float4*)(&Bs[br + i*8][bc]) =
                *(const float4*)(W + (size_t)(k0 + br + i*8) * D_ + col0 + bc);
        }
        __syncthreads();
        #pragma unroll
        for (int kk = 0; kk < 16; kk++) {
            float a[8], b[8];
            #pragma unroll
            for (int i = 0; i < 8; i++) a[i] = As[kk][ty*8 + i];
            #pragma unroll
            for (int j = 0; j < 8; j++) b[j] = Bs[kk][tx*8 + j];
            #pragma unroll
            for (int i = 0; i < 8; i++)
                #pragma unroll
                for (int j = 0; j < 8; j++)
                    acc[i][j] += a[i] * b[j];
        }
        __syncthreads();
    }

    #pragma unroll
    for (int i = 0; i < 8; i++) {
        const int r  = row0 + ty*8 + i;
        const int bb = r >> 10;          // /S_
        const int s  = r & (S_ - 1);
        #pragma unroll
        for (int j = 0; j < 8; j++) {
            const int c = col0 + tx*8 + j;
            const int h = c >> 6;        // /HD_
            const int d = c & 63;
            outp[(((size_t)(bb*H_ + h))*S_ + s)*HD_ + d] = acc[i][j] + bias[c];
        }
    }
}

// Same SGEMM, reads g_attn, writes row-major g_proj (Wo projection).
__global__ __launch_bounds__(256) void out_proj_kernel(
    const float* __restrict__ Wo, const float* __restrict__ bo)
{
    __shared__ float As[16][128];
    __shared__ float Bs[16][128];

    const int tid  = threadIdx.x;
    const int tx   = tid & 15;
    const int ty   = tid >> 4;
    const int row0 = blockIdx.y * 128;
    const int col0 = blockIdx.x * 128;

    const int ar = tid >> 2;
    const int ac = (tid & 3) << 2;
    const int br = tid >> 5;
    const int bc = (tid & 31) << 2;

    float acc[8][8];
    #pragma unroll
    for (int i = 0; i < 8; i++)
        #pragma unroll
        for (int j = 0; j < 8; j++) acc[i][j] = 0.f;

    for (int k0 = 0; k0 < D_; k0 += 16) {
        #pragma unroll
        for (int i = 0; i < 2; i++) {
            float4 a = *(const float4*)(g_attn + (size_t)(row0 + ar + i*64) * D_ + k0 + ac);
            As[ac+0][ar + i*64] = a.x;
            As[ac+1][ar + i*64] = a.y;
            As[ac+2][ar + i*64] = a.z;
            As[ac+3][ar + i*64] = a.w;
        }
        #pragma unroll
        for (int i = 0; i < 2; i++) {
            *(float4*)(&Bs[br + i*8][bc]) =
                *(const float4*)(Wo + (size_t)(k0 + br + i*8) * D_ + col0 + bc);
        }
        __syncthreads();
        #pragma unroll
        for (int kk = 0; kk < 16; kk++) {
            float a[8], b[8];
            #pragma unroll
            for (int i = 0; i < 8; i++) a[i] = As[kk][ty*8 + i];
            #pragma unroll
            for (int j = 0; j < 8; j++) b[j] = Bs[kk][tx*8 + j];
            #pragma unroll
            for (int i = 0; i < 8; i++)
                #pragma unroll
                for (int j = 0; j < 8; j++)
                    acc[i][j] += a[i] * b[j];
        }
        __syncthreads();
    }

    #pragma unroll
    for (int i = 0; i < 8; i++) {
        const int r = row0 + ty*8 + i;
        #pragma unroll
        for (int j = 0; j < 8; j++) {
            const int c = col0 + tx*8 + j;
            g_proj[(size_t)r * D_ + c] = acc[i][j] + bo[c];
        }
    }
}

// ============================================================
// Flash attention (causal). One CTA per (64-row q-tile, b*h).
// 256 threads = 16x16; each thread owns a 4x4 tile of S and O.
// Q,K stored d-major in smem (conflict-free LDS.128 in QK^T loop).
// ============================================================
__global__ __launch_bounds__(256) void attn_kernel(const int* __restrict__ mask)
{
    extern __shared__ float sm[];
    float (*Qs)[64]  = (float(*)[64])(sm);                          // Qs[d][r]
    float (*Kst)[68] = (float(*)[68])(sm + 64*64);                  // Kst[d][c]
    float (*Vs)[64]  = (float(*)[64])(sm + 64*64 + 64*68);          // Vs[k][d]
    float (*Ps)[68]  = (float(*)[68])(sm + 64*64 + 64*68 + 64*64);  // Ps[r][k]

    const int qt = (int)gridDim.x - 1 - (int)blockIdx.x;  // heavy tiles first
    const int bh = blockIdx.y;
    const int b  = bh >> 4;
    const int h  = bh & 15;

    const int tid = threadIdx.x;
    const int tx  = tid & 15;
    const int ty  = tid >> 4;

    const float* __restrict__ Qg = g_Q + (size_t)bh * S_ * HD_;
    const float* __restrict__ Kg = g_K + (size_t)bh * S_ * HD_;
    const float* __restrict__ Vg = g_V + (size_t)bh * S_ * HD_;

    const int lr = tid >> 2;          // 0..63
    const int lc = (tid & 3) << 4;    // 0,16,32,48

    // Q tile -> smem, transposed to d-major
    #pragma unroll
    for (int i = 0; i < 4; i++) {
        float4 v = *(const float4*)(Qg + (size_t)(qt*64 + lr) * HD_ + lc + i*4);
        Qs[lc + i*4 + 0][lr] = v.x;
        Qs[lc + i*4 + 1][lr] = v.y;
        Qs[lc + i*4 + 2][lr] = v.z;
        Qs[lc + i*4 + 3][lr] = v.w;
    }

    float m_i[4], l_i[4], o[4][4];
    #pragma unroll
    for (int i = 0; i < 4; i++) {
        m_i[i] = -1e30f; l_i[i] = 0.f;
        #pragma unroll
        for (int j = 0; j < 4; j++) o[i][j] = 0.f;
    }

    const int qrow0 = qt*64 + ty*4;

    for (int j = 0; j <= qt; j++) {
        __syncthreads();   // previous PV done (and Q store visible on iter 0)
        #pragma unroll
        for (int i = 0; i < 4; i++) {
            float4 kv = *(const float4*)(Kg + (size_t)(j*64 + lr) * HD_ + lc + i*4);
            Kst[lc + i*4 + 0][lr] = kv.x;
            Kst[lc + i*4 + 1][lr] = kv.y;
            Kst[lc + i*4 + 2][lr] = kv.z;
            Kst[lc + i*4 + 3][lr] = kv.w;
            *(float4*)(&Vs[lr][lc + i*4]) =
                *(const float4*)(Vg + (size_t)(j*64 + lr) * HD_ + lc + i*4);
        }
        __syncthreads();

        // S = Q K^T
        float sreg[4][4];
        #pragma unroll
        for (int i = 0; i < 4; i++)
            #pragma unroll
            for (int jj = 0; jj < 4; jj++) sreg[i][jj] = 0.f;

        #pragma unroll 16
        for (int d = 0; d < 64; d++) {
            float4 qa = *(const float4*)(&Qs[d][ty*4]);
            float4 kb = *(const float4*)(&Kst[d][tx*4]);
            float qv[4] = {qa.x, qa.y, qa.z, qa.w};
            float kv[4] = {kb.x, kb.y, kb.z, kb.w};
            #pragma unroll
            for (int i = 0; i < 4; i++)
                #pragma unroll
                for (int jj = 0; jj < 4; jj++)
                    sreg[i][jj] += qv[i] * kv[jj];
        }

        // scale + causal + input mask
        const int kc0 = j*64 + tx*4;
        int mk[4];
        #pragma unroll
        for (int jj = 0; jj < 4; jj++) mk[jj] = mask[b*S_ + kc0 + jj];
        #pragma unroll
        for (int i = 0; i < 4; i++) {
            const int qr = qrow0 + i;
            #pragma unroll
            for (int jj = 0; jj < 4; jj++) {
                float v = sreg[i][jj] * 0.125f;
                if ((kc0 + jj) > qr || mk[jj] == 0) v = -1e9f;
                sreg[i][jj] = v;
            }
        }

        // online softmax (row groups = 16-lane halves of the warp)
        #pragma unroll
        for (int i = 0; i < 4; i++) {
            float rm = fmaxf(fmaxf(sreg[i][0], sreg[i][1]),
                             fmaxf(sreg[i][2], sreg[i][3]));
            #pragma unroll
            for (int off = 8; off >= 1; off >>= 1)
                rm = fmaxf(rm, __shfl_xor_sync(0xffffffffu, rm, off));
            const float mn   = fmaxf(m_i[i], rm);
            const float corr = __expf(m_i[i] - mn);
            m_i[i] = mn;
            float rs = 0.f;
            #pragma unroll
            for (int jj = 0; jj < 4; jj++) {
                float p = __expf(sreg[i][jj] - mn);
                sreg[i][jj] = p;
                rs += p;
            }
            #pragma unroll
            for (int off = 8; off >= 1; off >>= 1)
                rs += __shfl_xor_sync(0xffffffffu, rs, off);
            l_i[i] = l_i[i] * corr + rs;
            #pragma unroll
            for (int jj = 0; jj < 4; jj++) o[i][jj] *= corr;
            #pragma unroll
            for (int jj = 0; jj < 4; jj++)
                Ps[ty*4 + i][tx*4 + jj] = sreg[i][jj];
        }
        __syncthreads();

        // O += P @ V
        #pragma unroll 8
        for (int kk = 0; kk < 64; kk++) {
            float p0 = Ps[ty*4 + 0][kk];
            float p1 = Ps[ty*4 + 1][kk];
            float p2 = Ps[ty*4 + 2][kk];
            float p3 = Ps[ty*4 + 3][kk];
            float4 vv = *(const float4*)(&Vs[kk][tx*4]);
            o[0][0] += p0*vv.x; o[0][1] += p0*vv.y; o[0][2] += p0*vv.z; o[0][3] += p0*vv.w;
            o[1][0] += p1*vv.x; o[1][1] += p1*vv.y; o[1][2] += p1*vv.z; o[1][3] += p1*vv.w;
            o[2][0] += p2*vv.x; o[2][1] += p2*vv.y; o[2][2] += p2*vv.z; o[2][3] += p2*vv.w;
            o[3][0] += p3*vv.x; o[3][1] += p3*vv.y; o[3][2] += p3*vv.z; o[3][3] += p3*vv.w;
        }
    }

    // normalize + write [B,S,D] with col = h*64+d
    #pragma unroll
    for (int i = 0; i < 4; i++) {
        const float inv = 1.f / l_i[i];
        const int qr = qrow0 + i;
        float4 r;
        r.x = o[i][0] * inv; r.y = o[i][1] * inv;
        r.z = o[i][2] * inv; r.w = o[i][3] * inv;
        *(float4*)(&g_attn[((size_t)(b*S_ + qr))*D_ + h*64 + tx*4]) = r;
    }
}

// ============================================================
// Residual add + LayerNorm (unbiased var /1023, eps added to std)
// ============================================================
__global__ __launch_bounds__(256) void ln_kernel(
    const float* __restrict__ query,
    const float* __restrict__ lw, const float* __restrict__ lb,
    float* __restrict__ out)
{
    __shared__ float xs[D_];
    __shared__ float red[8];
    const int r   = blockIdx.x;
    const int tid = threadIdx.x;
    const size_t base = (size_t)r * D_;

    float s = 0.f;
    #pragma unroll
    for (int i = tid; i < D_; i += 256) {
        float v = g_proj[base + i] + query[base + i];
        xs[i] = v;
        s += v;
    }
    #pragma unroll
    for (int off = 16; off >= 1; off >>= 1) s += __shfl_xor_sync(~0u, s, off);
    if ((tid & 31) == 0) red[tid >> 5] = s;
    __syncthreads();
    if (tid < 32) {
        float t = (tid < 8) ? red[tid] : 0.f;
        #pragma unroll
        for (int off = 4; off >= 1; off >>= 1) t += __shfl_xor_sync(~0u, t, off);
        if (tid == 0) red[0] = t;
    }
    __syncthreads();
    const float mean = red[0] * (1.f / (float)D_);
    __syncthreads();

    float sv = 0.f;
    #pragma unroll
    for (int i = tid; i < D_; i += 256) {
        float d = xs[i] - mean;
        sv += d * d;
    }
    #pragma unroll
    for (int off = 16; off >= 1; off >>= 1) sv += __shfl_xor_sync(~0u, sv, off);
    if ((tid & 31) == 0) red[tid >> 5] = sv;
    __syncthreads();
    if (tid < 32) {
        float t = (tid < 8) ? red[tid] : 0.f;
        #pragma unroll
        for (int off = 4; off >= 1; off >>= 1) t += __shfl_xor_sync(~0u, t, off);
        if (tid == 0) red[0] = t;
    }
    __syncthreads();
    const float var = red[0] * (1.f / (float)(D_ - 1));
    const float inv = 1.f / (sqrtf(var) + 1e-6f);

    #pragma unroll
    for (int i = tid; i < D_; i += 256)
        out[base + i] = lw[i] * (xs[i] - mean) * inv + lb[i];
}

// ============================================================
extern "C" void kernel_launch(void* const* d_in, const int* in_sizes, int n_in,
                              void* d_out, int out_size)
{
    const float* query = (const float*)d_in[0];
    const float* key   = (const float*)d_in[1];
    const float* value = (const float*)d_in[2];
    const int*   mask  = (const int*)  d_in[3];
    const float* Wq    = (const float*)d_in[4];
    const float* bq    = (const float*)d_in[5];
    const float* Wk    = (const float*)d_in[6];
    const float* bk    = (const float*)d_in[7];
    const float* Wv    = (const float*)d_in[8];
    const float* bv    = (const float*)d_in[9];
    const float* Wo    = (const float*)d_in[10];
    const float* bo    = (const float*)d_in[11];
    const float* ln_w  = (const float*)d_in[12];
    const float* ln_b  = (const float*)d_in[13];
    float* out = (float*)d_out;

    const size_t ATTN_SMEM = (size_t)(64*64 + 64*68 + 64*64 + 64*68) * sizeof(float);
    cudaFuncSetAttribute(attn_kernel, cudaFuncAttributeMaxDynamicSharedMemorySize,
                         (int)ATTN_SMEM);

    qkv_proj_kernel<<<dim3(8, 32, 3), 256>>>(query, key, value,
                                             Wq, bq, Wk, bk, Wv, bv);
    attn_kernel<<<dim3(16, 64), 256, ATTN_SMEM>>>(mask);
    out_proj_kernel<<<dim3(8, 32), 256>>>(Wo, bo);
    ln_kernel<<<B_*S_, 256>>>(query, ln_w, ln_b, out);
}

// round 2
// speedup vs baseline: 1.6508x; 1.6508x over previous
#include <cuda_runtime.h>
#include <math.h>
#include <stdint.h>

#define B_  4
#define S_  1024
#define D_  1024
#define H_  16
#define HD_ 64

// ---- scratch (no cudaMalloc allowed) ----
__device__ float g_Q[B_*H_*S_*HD_];     // [B,H,S,HD]
__device__ float g_K[B_*H_*S_*HD_];
__device__ float g_V[B_*H_*S_*HD_];
__device__ float g_attn[B_*S_*D_];      // [B,S,D]
__device__ float g_proj[B_*S_*D_];      // after Wo projection

__device__ __forceinline__ uint32_t f2tf(float x) {
    uint32_t u;
    asm("cvt.rna.tf32.f32 %0, %1;" : "=r"(u) : "f"(x));
    return u;
}

__device__ __forceinline__ void mma_tf32(float c[4], const uint32_t a[4],
                                         const uint32_t b[2]) {
    asm volatile(
        "mma.sync.aligned.m16n8k8.row.col.f32.tf32.tf32.f32 "
        "{%0,%1,%2,%3}, {%4,%5,%6,%7}, {%8,%9}, {%0,%1,%2,%3};"
        : "+f"(c[0]), "+f"(c[1]), "+f"(c[2]), "+f"(c[3])
        : "r"(a[0]), "r"(a[1]), "r"(a[2]), "r"(a[3]), "r"(b[0]), "r"(b[1]));
}

// ============================================================
// tf32 tensor-core GEMM: out = X[M,1024] @ W[1024,1024] + bias
// CTA tile 128x128, BK=16, 8 warps, warp tile 64x32.
// MODE 0: scatter to [B,H,S,HD]; MODE 1: row-major [M,1024].
// ============================================================
template <int MODE>
__device__ __forceinline__ void gemm_tf32_body(
    const float* __restrict__ X, const float* __restrict__ W,
    const float* __restrict__ bias, float* __restrict__ outp)
{
    __shared__ uint32_t As[128][20];   // [m][k], pad -> conflict-free frags
    __shared__ uint32_t Bs[16][136];   // [k][n], pad -> conflict-free frags

    const int tid    = threadIdx.x;
    const int wid    = tid >> 5;
    const int lane   = tid & 31;
    const int warp_m = wid & 1;        // 0..1 (64 rows each)
    const int warp_n = wid >> 1;       // 0..3 (32 cols each)
    const int g      = lane >> 2;      // 0..7
    const int tg     = lane & 3;       // 0..3

    const int row0 = blockIdx.y * 128;
    const int col0 = blockIdx.x * 128;

    // global-load mapping
    const int ar  = tid >> 2;          // 0..63
    const int ac  = (tid & 3) << 2;    // 0,4,8,12
    const int bkr = tid >> 5;          // 0..7
    const int bnc = (tid & 31) << 2;   // 0..124

    float4 a_reg0, a_reg1, b_reg0, b_reg1;
    a_reg0 = *(const float4*)(X + (size_t)(row0 + ar)      * D_ + ac);
    a_reg1 = *(const float4*)(X + (size_t)(row0 + ar + 64) * D_ + ac);
    b_reg0 = *(const float4*)(W + (size_t)(bkr)     * D_ + col0 + bnc);
    b_reg1 = *(const float4*)(W + (size_t)(bkr + 8) * D_ + col0 + bnc);

    float acc[4][4][4];
    #pragma unroll
    for (int mt = 0; mt < 4; mt++)
        #pragma unroll
        for (int nt = 0; nt < 4; nt++)
            #pragma unroll
            for (int i = 0; i < 4; i++) acc[mt][nt][i] = 0.f;

    for (int k0 = 0; k0 < D_; k0 += 16) {
        __syncthreads();   // previous compute done before overwriting smem
        {
            uint4 u;
            u.x = f2tf(a_reg0.x); u.y = f2tf(a_reg0.y);
            u.z = f2tf(a_reg0.z); u.w = f2tf(a_reg0.w);
            *(uint4*)(&As[ar][ac]) = u;
            u.x = f2tf(a_reg1.x); u.y = f2tf(a_reg1.y);
            u.z = f2tf(a_reg1.z); u.w = f2tf(a_reg1.w);
            *(uint4*)(&As[ar + 64][ac]) = u;
            u.x = f2tf(b_reg0.x); u.y = f2tf(b_reg0.y);
            u.z = f2tf(b_reg0.z); u.w = f2tf(b_reg0.w);
            *(uint4*)(&Bs[bkr][bnc]) = u;
            u.x = f2tf(b_reg1.x); u.y = f2tf(b_reg1.y);
            u.z = f2tf(b_reg1.z); u.w = f2tf(b_reg1.w);
            *(uint4*)(&Bs[bkr + 8][bnc]) = u;
        }
        __syncthreads();

        // prefetch next K tile
        if (k0 + 16 < D_) {
            const int kn = k0 + 16;
            a_reg0 = *(const float4*)(X + (size_t)(row0 + ar)      * D_ + kn + ac);
            a_reg1 = *(const float4*)(X + (size_t)(row0 + ar + 64) * D_ + kn + ac);
            b_reg0 = *(const float4*)(W + (size_t)(kn + bkr)     * D_ + col0 + bnc);
            b_reg1 = *(const float4*)(W + (size_t)(kn + bkr + 8) * D_ + col0 + bnc);
        }

        #pragma unroll
        for (int ks = 0; ks < 2; ks++) {
            const int kb = ks * 8;
            uint32_t af[4][4];
            #pragma unroll
            for (int mt = 0; mt < 4; mt++) {
                const int m = warp_m * 64 + mt * 16 + g;
                af[mt][0] = As[m][kb + tg];
                af[mt][1] = As[m + 8][kb + tg];
                af[mt][2] = As[m][kb + tg + 4];
                af[mt][3] = As[m + 8][kb + tg + 4];
            }
            uint32_t bf[4][2];
            #pragma unroll
            for (int nt = 0; nt < 4; nt++) {
                const int n = warp_n * 32 + nt * 8 + g;
                bf[nt][0] = Bs[kb + tg][n];
                bf[nt][1] = Bs[kb + tg + 4][n];
            }
            #pragma unroll
            for (int mt = 0; mt < 4; mt++)
                #pragma unroll
                for (int nt = 0; nt < 4; nt++)
                    mma_tf32(acc[mt][nt], af[mt], bf[nt]);
        }
    }

    // epilogue: bias + store (float2: cols 2tg, 2tg+1 contiguous)
    #pragma unroll
    for (int nt = 0; nt < 4; nt++) {
        const int c  = col0 + warp_n * 32 + nt * 8 + tg * 2;
        const float bx = bias[c];
        const float by = bias[c + 1];
        #pragma unroll
        for (int mt = 0; mt < 4; mt++) {
            const int r = row0 + warp_m * 64 + mt * 16 + g;
            float2 v0 = make_float2(acc[mt][nt][0] + bx, acc[mt][nt][1] + by);
            float2 v1 = make_float2(acc[mt][nt][2] + bx, acc[mt][nt][3] + by);
            if (MODE == 0) {
                const int h = c >> 6, d = c & 63;
                const int b0 = r >> 10,       s0 = r & (S_ - 1);
                const int b1 = (r + 8) >> 10, s1 = (r + 8) & (S_ - 1);
                *(float2*)(&outp[(((size_t)(b0 * H_ + h)) * S_ + s0) * HD_ + d]) = v0;
                *(float2*)(&outp[(((size_t)(b1 * H_ + h)) * S_ + s1) * HD_ + d]) = v1;
            } else {
                *(float2*)(&outp[(size_t)r * D_ + c])       = v0;
                *(float2*)(&outp[(size_t)(r + 8) * D_ + c]) = v1;
            }
        }
    }
}

__global__ __launch_bounds__(256, 1) void qkv_proj_kernel(
    const float* __restrict__ q_in, const float* __restrict__ k_in,
    const float* __restrict__ v_in,
    const float* __restrict__ Wq, const float* __restrict__ bq,
    const float* __restrict__ Wk, const float* __restrict__ bk,
    const float* __restrict__ Wv, const float* __restrict__ bv)
{
    const int z = blockIdx.z;
    const float* X    = (z == 0) ? q_in : (z == 1) ? k_in : v_in;
    const float* W    = (z == 0) ? Wq   : (z == 1) ? Wk   : Wv;
    const float* bias = (z == 0) ? bq   : (z == 1) ? bk   : bv;
    float* outp       = (z == 0) ? g_Q  : (z == 1) ? g_K  : g_V;
    gemm_tf32_body<0>(X, W, bias, outp);
}

__global__ __launch_bounds__(256, 1) void out_proj_kernel(
    const float* __restrict__ Wo, const float* __restrict__ bo)
{
    gemm_tf32_body<1>(g_attn, Wo, bo, g_proj);
}

// ============================================================
// Flash attention (causal), fp32 FFMA. One CTA per (64-row q-tile, b*h).
// ============================================================
__global__ __launch_bounds__(256) void attn_kernel(const int* __restrict__ mask)
{
    extern __shared__ float sm[];
    float (*Qs)[64]  = (float(*)[64])(sm);                          // Qs[d][r]
    float (*Kst)[68] = (float(*)[68])(sm + 64*64);                  // Kst[d][c]
    float (*Vs)[64]  = (float(*)[64])(sm + 64*64 + 64*68);          // Vs[k][d]
    float (*Ps)[68]  = (float(*)[68])(sm + 64*64 + 64*68 + 64*64);  // Ps[r][k]

    const int qt = (int)gridDim.x - 1 - (int)blockIdx.x;  // heavy tiles first
    const int bh = blockIdx.y;
    const int b  = bh >> 4;
    const int h  = bh & 15;

    const int tid = threadIdx.x;
    const int tx  = tid & 15;
    const int ty  = tid >> 4;

    const float* __restrict__ Qg = g_Q + (size_t)bh * S_ * HD_;
    const float* __restrict__ Kg = g_K + (size_t)bh * S_ * HD_;
    const float* __restrict__ Vg = g_V + (size_t)bh * S_ * HD_;

    const int lr = tid >> 2;          // 0..63
    const int lc = (tid & 3) << 4;    // 0,16,32,48

    #pragma unroll
    for (int i = 0; i < 4; i++) {
        float4 v = *(const float4*)(Qg + (size_t)(qt*64 + lr) * HD_ + lc + i*4);
        Qs[lc + i*4 + 0][lr] = v.x;
        Qs[lc + i*4 + 1][lr] = v.y;
        Qs[lc + i*4 + 2][lr] = v.z;
        Qs[lc + i*4 + 3][lr] = v.w;
    }

    float m_i[4], l_i[4], o[4][4];
    #pragma unroll
    for (int i = 0; i < 4; i++) {
        m_i[i] = -1e30f; l_i[i] = 0.f;
        #pragma unroll
        for (int j = 0; j < 4; j++) o[i][j] = 0.f;
    }

    const int qrow0 = qt*64 + ty*4;

    for (int j = 0; j <= qt; j++) {
        __syncthreads();
        #pragma unroll
        for (int i = 0; i < 4; i++) {
            float4 kv = *(const float4*)(Kg + (size_t)(j*64 + lr) * HD_ + lc + i*4);
            Kst[lc + i*4 + 0][lr] = kv.x;
            Kst[lc + i*4 + 1][lr] = kv.y;
            Kst[lc + i*4 + 2][lr] = kv.z;
            Kst[lc + i*4 + 3][lr] = kv.w;
            *(float4*)(&Vs[lr][lc + i*4]) =
                *(const float4*)(Vg + (size_t)(j*64 + lr) * HD_ + lc + i*4);
        }
        __syncthreads();

        float sreg[4][4];
        #pragma unroll
        for (int i = 0; i < 4; i++)
            #pragma unroll
            for (int jj = 0; jj < 4; jj++) sreg[i][jj] = 0.f;

        #pragma unroll 16
        for (int d = 0; d < 64; d++) {
            float4 qa = *(const float4*)(&Qs[d][ty*4]);
            float4 kb = *(const float4*)(&Kst[d][tx*4]);
            float qv[4] = {qa.x, qa.y, qa.z, qa.w};
            float kv[4] = {kb.x, kb.y, kb.z, kb.w};
            #pragma unroll
            for (int i = 0; i < 4; i++)
                #pragma unroll
                for (int jj = 0; jj < 4; jj++)
                    sreg[i][jj] += qv[i] * kv[jj];
        }

        const int kc0 = j*64 + tx*4;
        int mk[4];
        #pragma unroll
        for (int jj = 0; jj < 4; jj++) mk[jj] = mask[b*S_ + kc0 + jj];
        #pragma unroll
        for (int i = 0; i < 4; i++) {
            const int qr = qrow0 + i;
            #pragma unroll
            for (int jj = 0; jj < 4; jj++) {
                float v = sreg[i][jj] * 0.125f;
                if ((kc0 + jj) > qr || mk[jj] == 0) v = -1e9f;
                sreg[i][jj] = v;
            }
        }

        #pragma unroll
        for (int i = 0; i < 4; i++) {
            float rm = fmaxf(fmaxf(sreg[i][0], sreg[i][1]),
                             fmaxf(sreg[i][2], sreg[i][3]));
            #pragma unroll
            for (int off = 8; off >= 1; off >>= 1)
                rm = fmaxf(rm, __shfl_xor_sync(0xffffffffu, rm, off));
            const float mn   = fmaxf(m_i[i], rm);
            const float corr = __expf(m_i[i] - mn);
            m_i[i] = mn;
            float rs = 0.f;
            #pragma unroll
            for (int jj = 0; jj < 4; jj++) {
                float p = __expf(sreg[i][jj] - mn);
                sreg[i][jj] = p;
                rs += p;
            }
            #pragma unroll
            for (int off = 8; off >= 1; off >>= 1)
                rs += __shfl_xor_sync(0xffffffffu, rs, off);
            l_i[i] = l_i[i] * corr + rs;
            #pragma unroll
            for (int jj = 0; jj < 4; jj++) o[i][jj] *= corr;
            #pragma unroll
            for (int jj = 0; jj < 4; jj++)
                Ps[ty*4 + i][tx*4 + jj] = sreg[i][jj];
        }
        __syncthreads();

        #pragma unroll 8
        for (int kk = 0; kk < 64; kk++) {
            float p0 = Ps[ty*4 + 0][kk];
            float p1 = Ps[ty*4 + 1][kk];
            float p2 = Ps[ty*4 + 2][kk];
            float p3 = Ps[ty*4 + 3][kk];
            float4 vv = *(const float4*)(&Vs[kk][tx*4]);
            o[0][0] += p0*vv.x; o[0][1] += p0*vv.y; o[0][2] += p0*vv.z; o[0][3] += p0*vv.w;
            o[1][0] += p1*vv.x; o[1][1] += p1*vv.y; o[1][2] += p1*vv.z; o[1][3] += p1*vv.w;
            o[2][0] += p2*vv.x; o[2][1] += p2*vv.y; o[2][2] += p2*vv.z; o[2][3] += p2*vv.w;
            o[3][0] += p3*vv.x; o[3][1] += p3*vv.y; o[3][2] += p3*vv.z; o[3][3] += p3*vv.w;
        }
    }

    #pragma unroll
    for (int i = 0; i < 4; i++) {
        const float inv = 1.f / l_i[i];
        const int qr = qrow0 + i;
        float4 r;
        r.x = o[i][0] * inv; r.y = o[i][1] * inv;
        r.z = o[i][2] * inv; r.w = o[i][3] * inv;
        *(float4*)(&g_attn[((size_t)(b*S_ + qr))*D_ + h*64 + tx*4]) = r;
    }
}

// ============================================================
// Residual add + LayerNorm (unbiased var /1023, eps added to std)
// ============================================================
__global__ __launch_bounds__(256) void ln_kernel(
    const float* __restrict__ query,
    const float* __restrict__ lw, const float* __restrict__ lb,
    float* __restrict__ out)
{
    __shared__ float xs[D_];
    __shared__ float red[8];
    const int r   = blockIdx.x;
    const int tid = threadIdx.x;
    const size_t base = (size_t)r * D_;

    float s = 0.f;
    #pragma unroll
    for (int i = tid; i < D_; i += 256) {
        float v = g_proj[base + i] + query[base + i];
        xs[i] = v;
        s += v;
    }
    #pragma unroll
    for (int off = 16; off >= 1; off >>= 1) s += __shfl_xor_sync(~0u, s, off);
    if ((tid & 31) == 0) red[tid >> 5] = s;
    __syncthreads();
    if (tid < 32) {
        float t = (tid < 8) ? red[tid] : 0.f;
        #pragma unroll
        for (int off = 4; off >= 1; off >>= 1) t += __shfl_xor_sync(~0u, t, off);
        if (tid == 0) red[0] = t;
    }
    __syncthreads();
    const float mean = red[0] * (1.f / (float)D_);
    __syncthreads();

    float sv = 0.f;
    #pragma unroll
    for (int i = tid; i < D_; i += 256) {
        float d = xs[i] - mean;
        sv += d * d;
    }
    #pragma unroll
    for (int off = 16; off >= 1; off >>= 1) sv += __shfl_xor_sync(~0u, sv, off);
    if ((tid & 31) == 0) red[tid >> 5] = sv;
    __syncthreads();
    if (tid < 32) {
        float t = (tid < 8) ? red[tid] : 0.f;
        #pragma unroll
        for (int off = 4; off >= 1; off >>= 1) t += __shfl_xor_sync(~0u, t, off);
        if (tid == 0) red[0] = t;
    }
    __syncthreads();
    const float var = red[0] * (1.f / (float)(D_ - 1));
    const float inv = 1.f / (sqrtf(var) + 1e-6f);

    #pragma unroll
    for (int i = tid; i < D_; i += 256)
        out[base + i] = lw[i] * (xs[i] - mean) * inv + lb[i];
}

// ============================================================
extern "C" void kernel_launch(void* const* d_in, const int* in_sizes, int n_in,
                              void* d_out, int out_size)
{
    const float* query = (const float*)d_in[0];
    const float* key   = (const float*)d_in[1];
    const float* value = (const float*)d_in[2];
    const int*   mask  = (const int*)  d_in[3];
    const float* Wq    = (const float*)d_in[4];
    const float* bq    = (const float*)d_in[5];
    const float* Wk    = (const float*)d_in[6];
    const float* bk    = (const float*)d_in[7];
    const float* Wv    = (const float*)d_in[8];
    const float* bv    = (const float*)d_in[9];
    const float* Wo    = (const float*)d_in[10];
    const float* bo    = (const float*)d_in[11];
    const float* ln_w  = (const float*)d_in[12];
    const float* ln_b  = (const float*)d_in[13];
    float* out = (float*)d_out;

    const size_t ATTN_SMEM = (size_t)(64*64 + 64*68 + 64*64 + 64*68) * sizeof(float);
    cudaFuncSetAttribute(attn_kernel, cudaFuncAttributeMaxDynamicSharedMemorySize,
                         (int)ATTN_SMEM);

    qkv_proj_kernel<<<dim3(8, 32, 3), 256>>>(query, key, value,
                                             Wq, bq, Wk, bk, Wv, bv);
    attn_kernel<<<dim3(16, 64), 256, ATTN_SMEM>>>(mask);
    out_proj_kernel<<<dim3(8, 32), 256>>>(Wo, bo);
    ln_kernel<<<B_*S_, 256>>>(query, ln_w, ln_b, out);
}

// round 3
// speedup vs baseline: 2.1578x; 1.3072x over previous
#include <cuda_runtime.h>
#include <math.h>
#include <stdint.h>

#define B_  4
#define S_  1024
#define D_  1024
#define H_  16
#define HD_ 64

// ---- scratch (no cudaMalloc allowed) ----
__device__ float g_Q[B_*H_*S_*HD_];     // [B,H,S,HD]
__device__ float g_K[B_*H_*S_*HD_];
__device__ float g_V[B_*H_*S_*HD_];
__device__ float g_attn[B_*S_*D_];      // [B,S,D]
__device__ float g_proj[B_*S_*D_];      // after Wo projection

__device__ __forceinline__ uint32_t f2tf(float x) {
    uint32_t u;
    asm("cvt.rna.tf32.f32 %0, %1;" : "=r"(u) : "f"(x));
    return u;
}

__device__ __forceinline__ void mma_tf32(float c[4], const uint32_t a[4],
                                         const uint32_t b[2]) {
    asm volatile(
        "mma.sync.aligned.m16n8k8.row.col.f32.tf32.tf32.f32 "
        "{%0,%1,%2,%3}, {%4,%5,%6,%7}, {%8,%9}, {%0,%1,%2,%3};"
        : "+f"(c[0]), "+f"(c[1]), "+f"(c[2]), "+f"(c[3])
        : "r"(a[0]), "r"(a[1]), "r"(a[2]), "r"(a[3]), "r"(b[0]), "r"(b[1]));
}

// ============================================================
// tf32 tensor-core GEMM: out = X[M,1024] @ W[1024,1024] + bias
// ============================================================
template <int MODE>
__device__ __forceinline__ void gemm_tf32_body(
    const float* __restrict__ X, const float* __restrict__ W,
    const float* __restrict__ bias, float* __restrict__ outp)
{
    __shared__ uint32_t As[128][20];
    __shared__ uint32_t Bs[16][136];

    const int tid    = threadIdx.x;
    const int wid    = tid >> 5;
    const int lane   = tid & 31;
    const int warp_m = wid & 1;
    const int warp_n = wid >> 1;
    const int g      = lane >> 2;
    const int tg     = lane & 3;

    const int row0 = blockIdx.y * 128;
    const int col0 = blockIdx.x * 128;

    const int ar  = tid >> 2;
    const int ac  = (tid & 3) << 2;
    const int bkr = tid >> 5;
    const int bnc = (tid & 31) << 2;

    float4 a_reg0, a_reg1, b_reg0, b_reg1;
    a_reg0 = *(const float4*)(X + (size_t)(row0 + ar)      * D_ + ac);
    a_reg1 = *(const float4*)(X + (size_t)(row0 + ar + 64) * D_ + ac);
    b_reg0 = *(const float4*)(W + (size_t)(bkr)     * D_ + col0 + bnc);
    b_reg1 = *(const float4*)(W + (size_t)(bkr + 8) * D_ + col0 + bnc);

    float acc[4][4][4];
    #pragma unroll
    for (int mt = 0; mt < 4; mt++)
        #pragma unroll
        for (int nt = 0; nt < 4; nt++)
            #pragma unroll
            for (int i = 0; i < 4; i++) acc[mt][nt][i] = 0.f;

    for (int k0 = 0; k0 < D_; k0 += 16) {
        __syncthreads();
        {
            uint4 u;
            u.x = f2tf(a_reg0.x); u.y = f2tf(a_reg0.y);
            u.z = f2tf(a_reg0.z); u.w = f2tf(a_reg0.w);
            *(uint4*)(&As[ar][ac]) = u;
            u.x = f2tf(a_reg1.x); u.y = f2tf(a_reg1.y);
            u.z = f2tf(a_reg1.z); u.w = f2tf(a_reg1.w);
            *(uint4*)(&As[ar + 64][ac]) = u;
            u.x = f2tf(b_reg0.x); u.y = f2tf(b_reg0.y);
            u.z = f2tf(b_reg0.z); u.w = f2tf(b_reg0.w);
            *(uint4*)(&Bs[bkr][bnc]) = u;
            u.x = f2tf(b_reg1.x); u.y = f2tf(b_reg1.y);
            u.z = f2tf(b_reg1.z); u.w = f2tf(b_reg1.w);
            *(uint4*)(&Bs[bkr + 8][bnc]) = u;
        }
        __syncthreads();

        if (k0 + 16 < D_) {
            const int kn = k0 + 16;
            a_reg0 = *(const float4*)(X + (size_t)(row0 + ar)      * D_ + kn + ac);
            a_reg1 = *(const float4*)(X + (size_t)(row0 + ar + 64) * D_ + kn + ac);
            b_reg0 = *(const float4*)(W + (size_t)(kn + bkr)     * D_ + col0 + bnc);
            b_reg1 = *(const float4*)(W + (size_t)(kn + bkr + 8) * D_ + col0 + bnc);
        }

        #pragma unroll
        for (int ks = 0; ks < 2; ks++) {
            const int kb = ks * 8;
            uint32_t af[4][4];
            #pragma unroll
            for (int mt = 0; mt < 4; mt++) {
                const int m = warp_m * 64 + mt * 16 + g;
                af[mt][0] = As[m][kb + tg];
                af[mt][1] = As[m + 8][kb + tg];
                af[mt][2] = As[m][kb + tg + 4];
                af[mt][3] = As[m + 8][kb + tg + 4];
            }
            uint32_t bf[4][2];
            #pragma unroll
            for (int nt = 0; nt < 4; nt++) {
                const int n = warp_n * 32 + nt * 8 + g;
                bf[nt][0] = Bs[kb + tg][n];
                bf[nt][1] = Bs[kb + tg + 4][n];
            }
            #pragma unroll
            for (int mt = 0; mt < 4; mt++)
                #pragma unroll
                for (int nt = 0; nt < 4; nt++)
                    mma_tf32(acc[mt][nt], af[mt], bf[nt]);
        }
    }

    #pragma unroll
    for (int nt = 0; nt < 4; nt++) {
        const int c  = col0 + warp_n * 32 + nt * 8 + tg * 2;
        const float bx = bias[c];
        const float by = bias[c + 1];
        #pragma unroll
        for (int mt = 0; mt < 4; mt++) {
            const int r = row0 + warp_m * 64 + mt * 16 + g;
            float2 v0 = make_float2(acc[mt][nt][0] + bx, acc[mt][nt][1] + by);
            float2 v1 = make_float2(acc[mt][nt][2] + bx, acc[mt][nt][3] + by);
            if (MODE == 0) {
                const int h = c >> 6, d = c & 63;
                const int b0 = r >> 10,       s0 = r & (S_ - 1);
                const int b1 = (r + 8) >> 10, s1 = (r + 8) & (S_ - 1);
                *(float2*)(&outp[(((size_t)(b0 * H_ + h)) * S_ + s0) * HD_ + d]) = v0;
                *(float2*)(&outp[(((size_t)(b1 * H_ + h)) * S_ + s1) * HD_ + d]) = v1;
            } else {
                *(float2*)(&outp[(size_t)r * D_ + c])       = v0;
                *(float2*)(&outp[(size_t)(r + 8) * D_ + c]) = v1;
            }
        }
    }
}

__global__ __launch_bounds__(256, 1) void qkv_proj_kernel(
    const float* __restrict__ q_in, const float* __restrict__ k_in,
    const float* __restrict__ v_in,
    const float* __restrict__ Wq, const float* __restrict__ bq,
    const float* __restrict__ Wk, const float* __restrict__ bk,
    const float* __restrict__ Wv, const float* __restrict__ bv)
{
    const int z = blockIdx.z;
    const float* X    = (z == 0) ? q_in : (z == 1) ? k_in : v_in;
    const float* W    = (z == 0) ? Wq   : (z == 1) ? Wk   : Wv;
    const float* bias = (z == 0) ? bq   : (z == 1) ? bk   : bv;
    float* outp       = (z == 0) ? g_Q  : (z == 1) ? g_K  : g_V;
    gemm_tf32_body<0>(X, W, bias, outp);
}

__global__ __launch_bounds__(256, 1) void out_proj_kernel(
    const float* __restrict__ Wo, const float* __restrict__ bo)
{
    gemm_tf32_body<1>(g_attn, Wo, bo, g_proj);
}

// ============================================================
// Flash attention (causal) on tf32 tensor cores.
// 128 threads = 4 warps; CTA handles 64 q-rows; warp owns 16 rows.
// S-tile 64x64 per j-iteration.
// ============================================================
#define APAD 68
__global__ __launch_bounds__(128) void attn_kernel(const int* __restrict__ mask)
{
    extern __shared__ uint32_t asm_[];
    uint32_t (*Ks)[APAD] = (uint32_t(*)[APAD])(asm_);              // Ks[col][d]
    uint32_t (*Vs)[APAD] = (uint32_t(*)[APAD])(asm_ + 64*APAD);    // Vs[k][d]
    uint32_t (*Ps)[APAD] = (uint32_t(*)[APAD])(asm_ + 2*64*APAD);  // P / Q-staging
    float* Ms = (float*)(asm_ + 3*64*APAD);                        // mask addend[64]

    const int qt = (int)gridDim.x - 1 - (int)blockIdx.x;  // heavy tiles first
    const int bh = blockIdx.y;
    const int b  = bh >> 4;
    const int h  = bh & 15;

    const int tid  = threadIdx.x;
    const int wid  = tid >> 5;
    const int lane = tid & 31;
    const int g    = lane >> 2;
    const int tg   = lane & 3;
    const int m0   = wid * 16;

    const float* __restrict__ Qg = g_Q + (size_t)bh * S_ * HD_;
    const float* __restrict__ Kg = g_K + (size_t)bh * S_ * HD_;
    const float* __restrict__ Vg = g_V + (size_t)bh * S_ * HD_;

    const int lr    = tid >> 1;         // 0..63
    const int lhalf = (tid & 1) * 32;   // 0 or 32

    // ---- stage Q tile (tf32) into Ps rows owned by this warp, grab fragments
    #pragma unroll
    for (int i = 0; i < 8; i++) {
        float4 v = *(const float4*)(Qg + (size_t)(qt*64 + lr) * HD_ + lhalf + i*4);
        uint4 u;
        u.x = f2tf(v.x); u.y = f2tf(v.y); u.z = f2tf(v.z); u.w = f2tf(v.w);
        *(uint4*)(&Ps[lr][lhalf + i*4]) = u;
    }
    __syncwarp();

    uint32_t qf[8][4];
    #pragma unroll
    for (int ks = 0; ks < 8; ks++) {
        qf[ks][0] = Ps[m0 + g][ks*8 + tg];
        qf[ks][1] = Ps[m0 + g + 8][ks*8 + tg];
        qf[ks][2] = Ps[m0 + g][ks*8 + tg + 4];
        qf[ks][3] = Ps[m0 + g + 8][ks*8 + tg + 4];
    }

    float m_i[2] = {-1e30f, -1e30f};
    float l_i[2] = {0.f, 0.f};
    float o[8][4];
    #pragma unroll
    for (int dt = 0; dt < 8; dt++)
        #pragma unroll
        for (int i = 0; i < 4; i++) o[dt][i] = 0.f;

    const int qr0 = qt*64 + m0 + g;       // thread row 0 (row 1 = +8)

    for (int j = 0; j <= qt; j++) {
        __syncthreads();   // all warps done with Ks/Vs (and Ps Q-staging on iter 0)
        #pragma unroll
        for (int i = 0; i < 8; i++) {
            float4 kv = *(const float4*)(Kg + (size_t)(j*64 + lr) * HD_ + lhalf + i*4);
            float4 vv = *(const float4*)(Vg + (size_t)(j*64 + lr) * HD_ + lhalf + i*4);
            uint4 uk, uv;
            uk.x = f2tf(kv.x); uk.y = f2tf(kv.y); uk.z = f2tf(kv.z); uk.w = f2tf(kv.w);
            uv.x = f2tf(vv.x); uv.y = f2tf(vv.y); uv.z = f2tf(vv.z); uv.w = f2tf(vv.w);
            *(uint4*)(&Ks[lr][lhalf + i*4]) = uk;
            *(uint4*)(&Vs[lr][lhalf + i*4]) = uv;
        }
        if (tid < 64)
            Ms[tid] = (mask[b*S_ + j*64 + tid] == 0) ? -1e9f : 0.f;
        __syncthreads();

        // ---- S = Q K^T (16x64 per warp)
        float s[8][4];
        #pragma unroll
        for (int nt = 0; nt < 8; nt++)
            #pragma unroll
            for (int i = 0; i < 4; i++) s[nt][i] = 0.f;

        #pragma unroll
        for (int ks = 0; ks < 8; ks++) {
            #pragma unroll
            for (int nt = 0; nt < 8; nt++) {
                uint32_t bf[2];
                bf[0] = Ks[nt*8 + g][ks*8 + tg];
                bf[1] = Ks[nt*8 + g][ks*8 + tg + 4];
                mma_tf32(s[nt], qf[ks], bf);
            }
        }

        // ---- scale + mask
        const bool diag = (j == qt);
        #pragma unroll
        for (int nt = 0; nt < 8; nt++) {
            const int c0 = nt*8 + 2*tg;
            const float ma = Ms[c0];
            const float mb = Ms[c0 + 1];
            s[nt][0] = s[nt][0] * 0.125f + ma;
            s[nt][1] = s[nt][1] * 0.125f + mb;
            s[nt][2] = s[nt][2] * 0.125f + ma;
            s[nt][3] = s[nt][3] * 0.125f + mb;
            if (diag) {
                const int gc0 = j*64 + c0;
                if (gc0 > qr0)         s[nt][0] = -1e9f;
                if (gc0 + 1 > qr0)     s[nt][1] = -1e9f;
                if (gc0 > qr0 + 8)     s[nt][2] = -1e9f;
                if (gc0 + 1 > qr0 + 8) s[nt][3] = -1e9f;
            }
        }

        // ---- online softmax (rows g, g+8)
        float rm0 = -1e30f, rm1 = -1e30f;
        #pragma unroll
        for (int nt = 0; nt < 8; nt++) {
            rm0 = fmaxf(rm0, fmaxf(s[nt][0], s[nt][1]));
            rm1 = fmaxf(rm1, fmaxf(s[nt][2], s[nt][3]));
        }
        rm0 = fmaxf(rm0, __shfl_xor_sync(0xffffffffu, rm0, 1));
        rm0 = fmaxf(rm0, __shfl_xor_sync(0xffffffffu, rm0, 2));
        rm1 = fmaxf(rm1, __shfl_xor_sync(0xffffffffu, rm1, 1));
        rm1 = fmaxf(rm1, __shfl_xor_sync(0xffffffffu, rm1, 2));

        const float mn0 = fmaxf(m_i[0], rm0);
        const float mn1 = fmaxf(m_i[1], rm1);
        const float corr0 = __expf(m_i[0] - mn0);
        const float corr1 = __expf(m_i[1] - mn1);
        m_i[0] = mn0; m_i[1] = mn1;

        float rs0 = 0.f, rs1 = 0.f;
        #pragma unroll
        for (int nt = 0; nt < 8; nt++) {
            s[nt][0] = __expf(s[nt][0] - mn0);
            s[nt][1] = __expf(s[nt][1] - mn0);
            s[nt][2] = __expf(s[nt][2] - mn1);
            s[nt][3] = __expf(s[nt][3] - mn1);
            rs0 += s[nt][0] + s[nt][1];
            rs1 += s[nt][2] + s[nt][3];
        }
        rs0 += __shfl_xor_sync(0xffffffffu, rs0, 1);
        rs0 += __shfl_xor_sync(0xffffffffu, rs0, 2);
        rs1 += __shfl_xor_sync(0xffffffffu, rs1, 1);
        rs1 += __shfl_xor_sync(0xffffffffu, rs1, 2);
        l_i[0] = l_i[0] * corr0 + rs0;
        l_i[1] = l_i[1] * corr1 + rs1;

        #pragma unroll
        for (int dt = 0; dt < 8; dt++) {
            o[dt][0] *= corr0; o[dt][1] *= corr0;
            o[dt][2] *= corr1; o[dt][3] *= corr1;
        }

        // ---- P -> smem (tf32). Each warp touches only its own 16 rows.
        #pragma unroll
        for (int nt = 0; nt < 8; nt++) {
            uint2 u0 = make_uint2(f2tf(s[nt][0]), f2tf(s[nt][1]));
            uint2 u1 = make_uint2(f2tf(s[nt][2]), f2tf(s[nt][3]));
            *(uint2*)(&Ps[m0 + g][nt*8 + 2*tg])     = u0;
            *(uint2*)(&Ps[m0 + g + 8][nt*8 + 2*tg]) = u1;
        }
        __syncwarp();

        // ---- O += P @ V
        #pragma unroll
        for (int ks = 0; ks < 8; ks++) {
            uint32_t af[4];
            af[0] = Ps[m0 + g][ks*8 + tg];
            af[1] = Ps[m0 + g + 8][ks*8 + tg];
            af[2] = Ps[m0 + g][ks*8 + tg + 4];
            af[3] = Ps[m0 + g + 8][ks*8 + tg + 4];
            #pragma unroll
            for (int dt = 0; dt < 8; dt++) {
                uint32_t bf[2];
                bf[0] = Vs[ks*8 + tg][dt*8 + g];
                bf[1] = Vs[ks*8 + tg + 4][dt*8 + g];
                mma_tf32(o[dt], af, bf);
            }
        }
    }

    // ---- normalize + write [B,S,D]
    const float inv0 = 1.f / l_i[0];
    const float inv1 = 1.f / l_i[1];
    #pragma unroll
    for (int dt = 0; dt < 8; dt++) {
        const int c = h*64 + dt*8 + 2*tg;
        float2 v0 = make_float2(o[dt][0] * inv0, o[dt][1] * inv0);
        float2 v1 = make_float2(o[dt][2] * inv1, o[dt][3] * inv1);
        *(float2*)(&g_attn[((size_t)(b*S_ + qr0))*D_ + c])     = v0;
        *(float2*)(&g_attn[((size_t)(b*S_ + qr0 + 8))*D_ + c]) = v1;
    }
}

// ============================================================
// Residual add + LayerNorm (unbiased var /1023, eps added to std)
// ============================================================
__global__ __launch_bounds__(256) void ln_kernel(
    const float* __restrict__ query,
    const float* __restrict__ lw, const float* __restrict__ lb,
    float* __restrict__ out)
{
    __shared__ float xs[D_];
    __shared__ float red[8];
    const int r   = blockIdx.x;
    const int tid = threadIdx.x;
    const size_t base = (size_t)r * D_;

    float s = 0.f;
    #pragma unroll
    for (int i = tid; i < D_; i += 256) {
        float v = g_proj[base + i] + query[base + i];
        xs[i] = v;
        s += v;
    }
    #pragma unroll
    for (int off = 16; off >= 1; off >>= 1) s += __shfl_xor_sync(~0u, s, off);
    if ((tid & 31) == 0) red[tid >> 5] = s;
    __syncthreads();
    if (tid < 32) {
        float t = (tid < 8) ? red[tid] : 0.f;
        #pragma unroll
        for (int off = 4; off >= 1; off >>= 1) t += __shfl_xor_sync(~0u, t, off);
        if (tid == 0) red[0] = t;
    }
    __syncthreads();
    const float mean = red[0] * (1.f / (float)D_);
    __syncthreads();

    float sv = 0.f;
    #pragma unroll
    for (int i = tid; i < D_; i += 256) {
        float d = xs[i] - mean;
        sv += d * d;
    }
    #pragma unroll
    for (int off = 16; off >= 1; off >>= 1) sv += __shfl_xor_sync(~0u, sv, off);
    if ((tid & 31) == 0) red[tid >> 5] = sv;
    __syncthreads();
    if (tid < 32) {
        float t = (tid < 8) ? red[tid] : 0.f;
        #pragma unroll
        for (int off = 4; off >= 1; off >>= 1) t += __shfl_xor_sync(~0u, t, off);
        if (tid == 0) red[0] = t;
    }
    __syncthreads();
    const float var = red[0] * (1.f / (float)(D_ - 1));
    const float inv = 1.f / (sqrtf(var) + 1e-6f);

    #pragma unroll
    for (int i = tid; i < D_; i += 256)
        out[base + i] = lw[i] * (xs[i] - mean) * inv + lb[i];
}

// ============================================================
extern "C" void kernel_launch(void* const* d_in, const int* in_sizes, int n_in,
                              void* d_out, int out_size)
{
    const float* query = (const float*)d_in[0];
    const float* key   = (const float*)d_in[1];
    const float* value = (const float*)d_in[2];
    const int*   mask  = (const int*)  d_in[3];
    const float* Wq    = (const float*)d_in[4];
    const float* bq    = (const float*)d_in[5];
    const float* Wk    = (const float*)d_in[6];
    const float* bk    = (const float*)d_in[7];
    const float* Wv    = (const float*)d_in[8];
    const float* bv    = (const float*)d_in[9];
    const float* Wo    = (const float*)d_in[10];
    const float* bo    = (const float*)d_in[11];
    const float* ln_w  = (const float*)d_in[12];
    const float* ln_b  = (const float*)d_in[13];
    float* out = (float*)d_out;

    const size_t ATTN_SMEM = (size_t)(3*64*APAD + 64) * sizeof(uint32_t);
    cudaFuncSetAttribute(attn_kernel, cudaFuncAttributeMaxDynamicSharedMemorySize,
                         (int)ATTN_SMEM);

    qkv_proj_kernel<<<dim3(8, 32, 3), 256>>>(query, key, value,
                                             Wq, bq, Wk, bk, Wv, bv);
    attn_kernel<<<dim3(16, 64), 128, ATTN_SMEM>>>(mask);
    out_proj_kernel<<<dim3(8, 32), 256>>>(Wo, bo);
    ln_kernel<<<B_*S_, 256>>>(query, ln_w, ln_b, out);
}

// round 4
// speedup vs baseline: 4.8146x; 2.2312x over previous
#include <cuda_runtime.h>
#include <cuda_fp16.h>
#include <math.h>
#include <stdint.h>

#define B_   4
#define S_   1024
#define D_   1024
#define H_   16
#define HD_  64
#define MTOT (B_*S_)

// ---- scratch (no cudaMalloc allowed) ----
__device__ __align__(16) __half g_Xh[3][MTOT*D_];   // q,k,v inputs in half
__device__ __align__(16) __half g_WT[4][D_*D_];     // W^T in half: [n][k]
__device__ __align__(16) __half g_Qh[MTOT*D_];      // [B,H,S,HD]
__device__ __align__(16) __half g_Kh[MTOT*D_];
__device__ __align__(16) __half g_Vh[MTOT*D_];
__device__ __align__(16) __half g_attn_h[MTOT*D_];  // [B,S,D] half
__device__ __align__(16) float  g_proj[MTOT*D_];

__device__ __forceinline__ void mma_f16(float c[4], const uint32_t a[4],
                                        const uint32_t b[2]) {
    asm volatile(
        "mma.sync.aligned.m16n8k16.row.col.f32.f16.f16.f32 "
        "{%0,%1,%2,%3}, {%4,%5,%6,%7}, {%8,%9}, {%0,%1,%2,%3};"
        : "+f"(c[0]), "+f"(c[1]), "+f"(c[2]), "+f"(c[3])
        : "r"(a[0]), "r"(a[1]), "r"(a[2]), "r"(a[3]), "r"(b[0]), "r"(b[1]));
}

__device__ __forceinline__ void cp16(void* smem, const void* gmem) {
    uint32_t s = (uint32_t)__cvta_generic_to_shared(smem);
    asm volatile("cp.async.cg.shared.global [%0], [%1], 16;\n" :: "r"(s), "l"(gmem));
}
__device__ __forceinline__ void cp_commit() {
    asm volatile("cp.async.commit_group;\n");
}
__device__ __forceinline__ void cp_wait1() {
    asm volatile("cp.async.wait_group 1;\n");
}

// ============================================================
// converters
// ============================================================
__global__ __launch_bounds__(256) void conv_in_kernel(
    const float* __restrict__ q, const float* __restrict__ k,
    const float* __restrict__ v)
{
    const float* src = (blockIdx.y == 0) ? q : (blockIdx.y == 1) ? k : v;
    __half* dst = g_Xh[blockIdx.y];
    const int i = (blockIdx.x * 256 + threadIdx.x) * 4;
    float4 f = *(const float4*)(src + i);
    *(__half2*)(dst + i)     = __floats2half2_rn(f.x, f.y);
    *(__half2*)(dst + i + 2) = __floats2half2_rn(f.z, f.w);
}

__global__ __launch_bounds__(256) void conv_w_kernel(
    const float* __restrict__ Wq, const float* __restrict__ Wk,
    const float* __restrict__ Wv, const float* __restrict__ Wo)
{
    __shared__ float tile[32][33];
    const int z = blockIdx.z;
    const float* W = (z == 0) ? Wq : (z == 1) ? Wk : (z == 2) ? Wv : Wo;
    __half* WT = g_WT[z];
    const int tx = threadIdx.x & 31;
    const int ty = threadIdx.x >> 5;      // 0..7
    const int n0 = blockIdx.x * 32;
    const int k0 = blockIdx.y * 32;
    #pragma unroll
    for (int i = ty; i < 32; i += 8)
        tile[i][tx] = W[(size_t)(k0 + i) * D_ + n0 + tx];
    __syncthreads();
    #pragma unroll
    for (int i = ty; i < 32; i += 8)
        WT[(size_t)(n0 + i) * D_ + k0 + tx] = __float2half_rn(tile[tx][i]);
}

// ============================================================
// fp16 tensor-core GEMM: out = X[M,1024] @ W[1024,1024] + bias
// BK=32, cp.async double-buffer, 8 warps, warp tile 64x32.
// MODE 0: half out, scatter to [B,H,S,HD]; MODE 1: fp32 row-major.
// ============================================================
template <int MODE>
__device__ __forceinline__ void gemm_f16_body(
    const __half* __restrict__ X, const __half* __restrict__ WT,
    const float* __restrict__ bias, void* outp)
{
    __shared__ __align__(16) __half As[2][128][40];
    __shared__ __align__(16) __half Bs[2][128][40];

    const int tid    = threadIdx.x;
    const int wid    = tid >> 5;
    const int lane   = tid & 31;
    const int warp_m = wid & 1;
    const int warp_n = wid >> 1;
    const int g      = lane >> 2;
    const int tg     = lane & 3;

    const int row0 = blockIdx.y * 128;
    const int col0 = blockIdx.x * 128;

    const int lrow = tid >> 1;           // 0..127
    const int loff = (tid & 1) * 16;     // halves

    const __half* Abase = X  + (size_t)(row0 + lrow) * D_ + loff;
    const __half* Bbase = WT + (size_t)(col0 + lrow) * D_ + loff;

    auto load_stage = [&](int s, int k0) {
        cp16(&As[s][lrow][loff],     Abase + k0);
        cp16(&As[s][lrow][loff + 8], Abase + k0 + 8);
        cp16(&Bs[s][lrow][loff],     Bbase + k0);
        cp16(&Bs[s][lrow][loff + 8], Bbase + k0 + 8);
        cp_commit();
    };

    load_stage(0, 0);
    load_stage(1, 32);

    float acc[4][4][4];
    #pragma unroll
    for (int mt = 0; mt < 4; mt++)
        #pragma unroll
        for (int nt = 0; nt < 4; nt++)
            #pragma unroll
            for (int i = 0; i < 4; i++) acc[mt][nt][i] = 0.f;

    const int NIT = D_ / 32;   // 32
    for (int it = 0; it < NIT; it++) {
        cp_wait1();
        __syncthreads();
        const int s = it & 1;

        #pragma unroll
        for (int ks = 0; ks < 2; ks++) {
            const int kb = ks * 16;
            uint32_t af[4][4];
            #pragma unroll
            for (int mt = 0; mt < 4; mt++) {
                const int m = warp_m * 64 + mt * 16 + g;
                af[mt][0] = *(const uint32_t*)(&As[s][m][kb + 2*tg]);
                af[mt][1] = *(const uint32_t*)(&As[s][m + 8][kb + 2*tg]);
                af[mt][2] = *(const uint32_t*)(&As[s][m][kb + 8 + 2*tg]);
                af[mt][3] = *(const uint32_t*)(&As[s][m + 8][kb + 8 + 2*tg]);
            }
            uint32_t bf[4][2];
            #pragma unroll
            for (int nt = 0; nt < 4; nt++) {
                const int n = warp_n * 32 + nt * 8 + g;
                bf[nt][0] = *(const uint32_t*)(&Bs[s][n][kb + 2*tg]);
                bf[nt][1] = *(const uint32_t*)(&Bs[s][n][kb + 8 + 2*tg]);
            }
            #pragma unroll
            for (int mt = 0; mt < 4; mt++)
                #pragma unroll
                for (int nt = 0; nt < 4; nt++)
                    mma_f16(acc[mt][nt], af[mt], bf[nt]);
        }
        __syncthreads();
        // clamped unconditional issue keeps group counts uniform
        const int knext = (it + 2 < NIT) ? (it + 2) * 32 : 0;
        load_stage(s, knext);
    }

    #pragma unroll
    for (int nt = 0; nt < 4; nt++) {
        const int c  = col0 + warp_n * 32 + nt * 8 + tg * 2;
        const float bx = bias[c];
        const float by = bias[c + 1];
        #pragma unroll
        for (int mt = 0; mt < 4; mt++) {
            const int r = row0 + warp_m * 64 + mt * 16 + g;
            if (MODE == 0) {
                __half* oh = (__half*)outp;
                __half2 v0 = __floats2half2_rn(acc[mt][nt][0] + bx, acc[mt][nt][1] + by);
                __half2 v1 = __floats2half2_rn(acc[mt][nt][2] + bx, acc[mt][nt][3] + by);
                const int h = c >> 6, d = c & 63;
                const int b0 = r >> 10,       s0 = r & (S_ - 1);
                const int b1 = (r + 8) >> 10, s1 = (r + 8) & (S_ - 1);
                *(__half2*)(&oh[(((size_t)(b0 * H_ + h)) * S_ + s0) * HD_ + d]) = v0;
                *(__half2*)(&oh[(((size_t)(b1 * H_ + h)) * S_ + s1) * HD_ + d]) = v1;
            } else {
                float* of = (float*)outp;
                float2 v0 = make_float2(acc[mt][nt][0] + bx, acc[mt][nt][1] + by);
                float2 v1 = make_float2(acc[mt][nt][2] + bx, acc[mt][nt][3] + by);
                *(float2*)(&of[(size_t)r * D_ + c])       = v0;
                *(float2*)(&of[(size_t)(r + 8) * D_ + c]) = v1;
            }
        }
    }
}

__global__ __launch_bounds__(256, 2) void qkv_proj_kernel(
    const float* __restrict__ bq, const float* __restrict__ bk,
    const float* __restrict__ bv)
{
    const int z = blockIdx.z;
    const float* bias = (z == 0) ? bq : (z == 1) ? bk : bv;
    __half* outp = (z == 0) ? g_Qh : (z == 1) ? g_Kh : g_Vh;
    gemm_f16_body<0>(g_Xh[z], g_WT[z], bias, outp);
}

__global__ __launch_bounds__(256, 2) void out_proj_kernel(const float* __restrict__ bo)
{
    gemm_f16_body<1>(g_attn_h, g_WT[3], bo, g_proj);
}

// ============================================================
// Flash attention (causal), fp16 tensor cores.
// 128 threads = 4 warps; CTA = 64 q-rows; warp owns 16 rows.
// ============================================================
__global__ __launch_bounds__(128) void attn_kernel(const int* __restrict__ mask)
{
    __shared__ __align__(16) __half Ks[64][72];   // [col n][k d]
    __shared__ __align__(16) __half Vs[64][72];   // [k][d]
    __shared__ __align__(16) __half Ps[64][72];   // P / Q staging (warp-private rows)
    __shared__ float Ms[64];

    const int qt = (int)gridDim.x - 1 - (int)blockIdx.x;  // heavy tiles first
    const int bh = blockIdx.y;
    const int b  = bh >> 4;
    const int h  = bh & 15;

    const int tid  = threadIdx.x;
    const int wid  = tid >> 5;
    const int lane = tid & 31;
    const int g    = lane >> 2;
    const int tg   = lane & 3;
    const int m0   = wid * 16;

    const __half* __restrict__ Qg = g_Qh + (size_t)bh * S_ * HD_;
    const __half* __restrict__ Kg = g_Kh + (size_t)bh * S_ * HD_;
    const __half* __restrict__ Vg = g_Vh + (size_t)bh * S_ * HD_;

    // ---- stage this warp's Q rows into Ps (warp-private), grab fragments
    {
        const int r   = m0 + (lane >> 1);
        const int off = (lane & 1) * 32;
        const __half* Qrow = Qg + (size_t)(qt*64 + r) * HD_ + off;
        #pragma unroll
        for (int i = 0; i < 4; i++)
            *(uint4*)(&Ps[r][off + i*8]) = *(const uint4*)(Qrow + i*8);
    }
    __syncwarp();

    uint32_t qf[4][4];
    #pragma unroll
    for (int ks = 0; ks < 4; ks++) {
        const int kb = ks * 16;
        qf[ks][0] = *(const uint32_t*)(&Ps[m0 + g][kb + 2*tg]);
        qf[ks][1] = *(const uint32_t*)(&Ps[m0 + g + 8][kb + 2*tg]);
        qf[ks][2] = *(const uint32_t*)(&Ps[m0 + g][kb + 8 + 2*tg]);
        qf[ks][3] = *(const uint32_t*)(&Ps[m0 + g + 8][kb + 8 + 2*tg]);
    }

    float m_i[2] = {-1e30f, -1e30f};
    float l_i[2] = {0.f, 0.f};
    float o[8][4];
    #pragma unroll
    for (int dt = 0; dt < 8; dt++)
        #pragma unroll
        for (int i = 0; i < 4; i++) o[dt][i] = 0.f;

    const int qr0 = qt*64 + m0 + g;

    // ldmatrix lane address precompute (for V transpose loads)
    const int vrow_off = ((lane >> 3) & 1) * 8 + (lane & 7);
    const int vcol_off = ((lane >> 4) & 1) * 8;

    const int lr   = tid >> 1;
    const int loff = (tid & 1) * 32;

    for (int j = 0; j <= qt; j++) {
        __syncthreads();   // all warps done reading Ks/Vs from previous iter
        {
            const __half* Krow = Kg + (size_t)(j*64 + lr) * HD_ + loff;
            const __half* Vrow = Vg + (size_t)(j*64 + lr) * HD_ + loff;
            #pragma unroll
            for (int i = 0; i < 4; i++) {
                *(uint4*)(&Ks[lr][loff + i*8]) = *(const uint4*)(Krow + i*8);
                *(uint4*)(&Vs[lr][loff + i*8]) = *(const uint4*)(Vrow + i*8);
            }
        }
        if (tid < 64)
            Ms[tid] = (mask[b*S_ + j*64 + tid] == 0) ? -1e9f : 0.f;
        __syncthreads();

        // ---- S = Q K^T (16x64 per warp)
        float s[8][4];
        #pragma unroll
        for (int nt = 0; nt < 8; nt++)
            #pragma unroll
            for (int i = 0; i < 4; i++) s[nt][i] = 0.f;

        #pragma unroll
        for (int ks = 0; ks < 4; ks++) {
            const int kb = ks * 16;
            #pragma unroll
            for (int nt = 0; nt < 8; nt++) {
                uint32_t bf[2];
                bf[0] = *(const uint32_t*)(&Ks[nt*8 + g][kb + 2*tg]);
                bf[1] = *(const uint32_t*)(&Ks[nt*8 + g][kb + 8 + 2*tg]);
                mma_f16(s[nt], qf[ks], bf);
            }
        }

        // ---- scale + mask
        const bool diag = (j == qt);
        #pragma unroll
        for (int nt = 0; nt < 8; nt++) {
            const int c0 = nt*8 + 2*tg;
            const float ma = Ms[c0];
            const float mb = Ms[c0 + 1];
            s[nt][0] = s[nt][0] * 0.125f + ma;
            s[nt][1] = s[nt][1] * 0.125f + mb;
            s[nt][2] = s[nt][2] * 0.125f + ma;
            s[nt][3] = s[nt][3] * 0.125f + mb;
            if (diag) {
                const int gc0 = j*64 + c0;
                if (gc0 > qr0)         s[nt][0] = -1e9f;
                if (gc0 + 1 > qr0)     s[nt][1] = -1e9f;
                if (gc0 > qr0 + 8)     s[nt][2] = -1e9f;
                if (gc0 + 1 > qr0 + 8) s[nt][3] = -1e9f;
            }
        }

        // ---- online softmax (rows g, g+8)
        float rm0 = -1e30f, rm1 = -1e30f;
        #pragma unroll
        for (int nt = 0; nt < 8; nt++) {
            rm0 = fmaxf(rm0, fmaxf(s[nt][0], s[nt][1]));
            rm1 = fmaxf(rm1, fmaxf(s[nt][2], s[nt][3]));
        }
        rm0 = fmaxf(rm0, __shfl_xor_sync(0xffffffffu, rm0, 1));
        rm0 = fmaxf(rm0, __shfl_xor_sync(0xffffffffu, rm0, 2));
        rm1 = fmaxf(rm1, __shfl_xor_sync(0xffffffffu, rm1, 1));
        rm1 = fmaxf(rm1, __shfl_xor_sync(0xffffffffu, rm1, 2));

        const float mn0 = fmaxf(m_i[0], rm0);
        const float mn1 = fmaxf(m_i[1], rm1);
        const float corr0 = __expf(m_i[0] - mn0);
        const float corr1 = __expf(m_i[1] - mn1);
        m_i[0] = mn0; m_i[1] = mn1;

        float rs0 = 0.f, rs1 = 0.f;
        #pragma unroll
        for (int nt = 0; nt < 8; nt++) {
            s[nt][0] = __expf(s[nt][0] - mn0);
            s[nt][1] = __expf(s[nt][1] - mn0);
            s[nt][2] = __expf(s[nt][2] - mn1);
            s[nt][3] = __expf(s[nt][3] - mn1);
            rs0 += s[nt][0] + s[nt][1];
            rs1 += s[nt][2] + s[nt][3];
        }
        rs0 += __shfl_xor_sync(0xffffffffu, rs0, 1);
        rs0 += __shfl_xor_sync(0xffffffffu, rs0, 2);
        rs1 += __shfl_xor_sync(0xffffffffu, rs1, 1);
        rs1 += __shfl_xor_sync(0xffffffffu, rs1, 2);
        l_i[0] = l_i[0] * corr0 + rs0;
        l_i[1] = l_i[1] * corr1 + rs1;

        #pragma unroll
        for (int dt = 0; dt < 8; dt++) {
            o[dt][0] *= corr0; o[dt][1] *= corr0;
            o[dt][2] *= corr1; o[dt][3] *= corr1;
        }

        // ---- P -> smem half (warp-private rows)
        #pragma unroll
        for (int nt = 0; nt < 8; nt++) {
            *(__half2*)(&Ps[m0 + g][nt*8 + 2*tg]) =
                __floats2half2_rn(s[nt][0], s[nt][1]);
            *(__half2*)(&Ps[m0 + g + 8][nt*8 + 2*tg]) =
                __floats2half2_rn(s[nt][2], s[nt][3]);
        }
        __syncwarp();

        // ---- O += P @ V  (V frags via ldmatrix.trans)
        #pragma unroll
        for (int ks = 0; ks < 4; ks++) {
            const int kb = ks * 16;
            uint32_t af[4];
            af[0] = *(const uint32_t*)(&Ps[m0 + g][kb + 2*tg]);
            af[1] = *(const uint32_t*)(&Ps[m0 + g + 8][kb + 2*tg]);
            af[2] = *(const uint32_t*)(&Ps[m0 + g][kb + 8 + 2*tg]);
            af[3] = *(const uint32_t*)(&Ps[m0 + g + 8][kb + 8 + 2*tg]);
            #pragma unroll
            for (int dt2 = 0; dt2 < 4; dt2++) {
                const int d0 = dt2 * 16;
                uint32_t r0, r1, r2, r3;
                uint32_t addr = (uint32_t)__cvta_generic_to_shared(
                    &Vs[kb + vrow_off][d0 + vcol_off]);
                asm volatile(
                    "ldmatrix.sync.aligned.m8n8.x4.trans.shared.b16 "
                    "{%0,%1,%2,%3}, [%4];"
                    : "=r"(r0), "=r"(r1), "=r"(r2), "=r"(r3) : "r"(addr));
                uint32_t bfa[2] = {r0, r1};
                uint32_t bfb[2] = {r2, r3};
                mma_f16(o[dt2*2],     af, bfa);
                mma_f16(o[dt2*2 + 1], af, bfb);
            }
        }
    }

    // ---- normalize + write half [B,S,D]
    const float inv0 = 1.f / l_i[0];
    const float inv1 = 1.f / l_i[1];
    #pragma unroll
    for (int dt = 0; dt < 8; dt++) {
        const int c = h*64 + dt*8 + 2*tg;
        *(__half2*)(&g_attn_h[((size_t)(b*S_ + qr0))*D_ + c]) =
            __floats2half2_rn(o[dt][0] * inv0, o[dt][1] * inv0);
        *(__half2*)(&g_attn_h[((size_t)(b*S_ + qr0 + 8))*D_ + c]) =
            __floats2half2_rn(o[dt][2] * inv1, o[dt][3] * inv1);
    }
}

// ============================================================
// Residual add + LayerNorm (unbiased var /1023, eps added to std)
// ============================================================
__global__ __launch_bounds__(256) void ln_kernel(
    const float* __restrict__ query,
    const float* __restrict__ lw, const float* __restrict__ lb,
    float* __restrict__ out)
{
    __shared__ float xs[D_];
    __shared__ float red[8];
    const int r   = blockIdx.x;
    const int tid = threadIdx.x;
    const size_t base = (size_t)r * D_;

    float s = 0.f;
    #pragma unroll
    for (int i = tid; i < D_; i += 256) {
        float v = g_proj[base + i] + query[base + i];
        xs[i] = v;
        s += v;
    }
    #pragma unroll
    for (int off = 16; off >= 1; off >>= 1) s += __shfl_xor_sync(~0u, s, off);
    if ((tid & 31) == 0) red[tid >> 5] = s;
    __syncthreads();
    if (tid < 32) {
        float t = (tid < 8) ? red[tid] : 0.f;
        #pragma unroll
        for (int off = 4; off >= 1; off >>= 1) t += __shfl_xor_sync(~0u, t, off);
        if (tid == 0) red[0] = t;
    }
    __syncthreads();
    const float mean = red[0] * (1.f / (float)D_);
    __syncthreads();

    float sv = 0.f;
    #pragma unroll
    for (int i = tid; i < D_; i += 256) {
        float d = xs[i] - mean;
        sv += d * d;
    }
    #pragma unroll
    for (int off = 16; off >= 1; off >>= 1) sv += __shfl_xor_sync(~0u, sv, off);
    if ((tid & 31) == 0) red[tid >> 5] = sv;
    __syncthreads();
    if (tid < 32) {
        float t = (tid < 8) ? red[tid] : 0.f;
        #pragma unroll
        for (int off = 4; off >= 1; off >>= 1) t += __shfl_xor_sync(~0u, t, off);
        if (tid == 0) red[0] = t;
    }
    __syncthreads();
    const float var = red[0] * (1.f / (float)(D_ - 1));
    const float inv = 1.f / (sqrtf(var) + 1e-6f);

    #pragma unroll
    for (int i = tid; i < D_; i += 256)
        out[base + i] = lw[i] * (xs[i] - mean) * inv + lb[i];
}

// ============================================================
extern "C" void kernel_launch(void* const* d_in, const int* in_sizes, int n_in,
                              void* d_out, int out_size)
{
    const float* query = (const float*)d_in[0];
    const float* key   = (const float*)d_in[1];
    const float* value = (const float*)d_in[2];
    const int*   mask  = (const int*)  d_in[3];
    const float* Wq    = (const float*)d_in[4];
    const float* bq    = (const float*)d_in[5];
    const float* Wk    = (const float*)d_in[6];
    const float* bk    = (const float*)d_in[7];
    const float* Wv    = (const float*)d_in[8];
    const float* bv    = (const float*)d_in[9];
    const float* Wo    = (const float*)d_in[10];
    const float* bo    = (const float*)d_in[11];
    const float* ln_w  = (const float*)d_in[12];
    const float* ln_b  = (const float*)d_in[13];
    float* out = (float*)d_out;

    conv_in_kernel<<<dim3(MTOT*D_/1024, 3), 256>>>(query, key, value);
    conv_w_kernel<<<dim3(32, 32, 4), 256>>>(Wq, Wk, Wv, Wo);
    qkv_proj_kernel<<<dim3(8, 32, 3), 256>>>(bq, bk, bv);
    attn_kernel<<<dim3(16, 64), 128>>>(mask);
    out_proj_kernel<<<dim3(8, 32), 256>>>(bo);
    ln_kernel<<<B_*S_, 256>>>(query, ln_w, ln_b, out);
}

// round 5
// speedup vs baseline: 5.3073x; 1.1023x over previous
#include <cuda_runtime.h>
#include <cuda_fp16.h>
#include <math.h>
#include <stdint.h>

#define B_   4
#define S_   1024
#define D_   1024
#define H_   16
#define HD_  64
#define MTOT (B_*S_)

// ---- scratch (no cudaMalloc allowed) ----
__device__ __align__(16) __half g_Xh[3][MTOT*D_];   // q,k,v inputs in half
__device__ __align__(16) __half g_WT[4][D_*D_];     // W^T in half: [n][k]
__device__ __align__(16) __half g_Qh[MTOT*D_];      // [B,H,S,HD]
__device__ __align__(16) __half g_Kh[MTOT*D_];
__device__ __align__(16) __half g_Vh[MTOT*D_];
__device__ __align__(16) __half g_attn_h[MTOT*D_];  // [B,S,D] half
__device__ __align__(16) float  g_proj[MTOT*D_];

__device__ __forceinline__ void mma_f16(float c[4], const uint32_t a[4],
                                        const uint32_t b[2]) {
    asm volatile(
        "mma.sync.aligned.m16n8k16.row.col.f32.f16.f16.f32 "
        "{%0,%1,%2,%3}, {%4,%5,%6,%7}, {%8,%9}, {%0,%1,%2,%3};"
        : "+f"(c[0]), "+f"(c[1]), "+f"(c[2]), "+f"(c[3])
        : "r"(a[0]), "r"(a[1]), "r"(a[2]), "r"(a[3]), "r"(b[0]), "r"(b[1]));
}

__device__ __forceinline__ void ldsm4(uint32_t r[4], const void* p) {
    uint32_t a = (uint32_t)__cvta_generic_to_shared(p);
    asm volatile("ldmatrix.sync.aligned.m8n8.x4.shared.b16 {%0,%1,%2,%3}, [%4];"
                 : "=r"(r[0]), "=r"(r[1]), "=r"(r[2]), "=r"(r[3]) : "r"(a));
}
__device__ __forceinline__ void ldsm4t(uint32_t r[4], const void* p) {
    uint32_t a = (uint32_t)__cvta_generic_to_shared(p);
    asm volatile("ldmatrix.sync.aligned.m8n8.x4.trans.shared.b16 {%0,%1,%2,%3}, [%4];"
                 : "=r"(r[0]), "=r"(r[1]), "=r"(r[2]), "=r"(r[3]) : "r"(a));
}

__device__ __forceinline__ uint32_t packh2(float x, float y) {
    __half2 h = __floats2half2_rn(x, y);
    return *(uint32_t*)&h;
}

__device__ __forceinline__ void cp16(void* smem, const void* gmem) {
    uint32_t s = (uint32_t)__cvta_generic_to_shared(smem);
    asm volatile("cp.async.cg.shared.global [%0], [%1], 16;\n" :: "r"(s), "l"(gmem));
}
__device__ __forceinline__ void cp_commit() {
    asm volatile("cp.async.commit_group;\n");
}
__device__ __forceinline__ void cp_wait1() {
    asm volatile("cp.async.wait_group 1;\n");
}

// ============================================================
// converters
// ============================================================
__global__ __launch_bounds__(256) void conv_in_kernel(
    const float* __restrict__ q, const float* __restrict__ k,
    const float* __restrict__ v)
{
    const float* src = (blockIdx.y == 0) ? q : (blockIdx.y == 1) ? k : v;
    __half* dst = g_Xh[blockIdx.y];
    const int i = (blockIdx.x * 256 + threadIdx.x) * 4;
    float4 f = *(const float4*)(src + i);
    *(__half2*)(dst + i)     = __floats2half2_rn(f.x, f.y);
    *(__half2*)(dst + i + 2) = __floats2half2_rn(f.z, f.w);
}

__global__ __launch_bounds__(256) void conv_w_kernel(
    const float* __restrict__ Wq, const float* __restrict__ Wk,
    const float* __restrict__ Wv, const float* __restrict__ Wo)
{
    __shared__ float tile[32][33];
    const int z = blockIdx.z;
    const float* W = (z == 0) ? Wq : (z == 1) ? Wk : (z == 2) ? Wv : Wo;
    __half* WT = g_WT[z];
    const int tx = threadIdx.x & 31;
    const int ty = threadIdx.x >> 5;
    const int n0 = blockIdx.x * 32;
    const int k0 = blockIdx.y * 32;
    #pragma unroll
    for (int i = ty; i < 32; i += 8)
        tile[i][tx] = W[(size_t)(k0 + i) * D_ + n0 + tx];
    __syncthreads();
    #pragma unroll
    for (int i = ty; i < 32; i += 8)
        WT[(size_t)(n0 + i) * D_ + k0 + tx] = __float2half_rn(tile[tx][i]);
}

// ============================================================
// fp16 tensor-core GEMM: out = X[M,1024] @ W[1024,1024] + bias
// BK=32, cp.async double-buffer, 8 warps, warp tile 64x32, ldmatrix frags.
// ============================================================
template <int MODE>
__device__ __forceinline__ void gemm_f16_body(
    const __half* __restrict__ X, const __half* __restrict__ WT,
    const float* __restrict__ bias, void* outp)
{
    __shared__ __align__(16) __half As[2][128][40];
    __shared__ __align__(16) __half Bs[2][128][40];

    const int tid    = threadIdx.x;
    const int wid    = tid >> 5;
    const int lane   = tid & 31;
    const int warp_m = wid & 1;
    const int warp_n = wid >> 1;
    const int g      = lane >> 2;
    const int tg     = lane & 3;

    const int row0 = blockIdx.y * 128;
    const int col0 = blockIdx.x * 128;

    const int lrow = tid >> 1;
    const int loff = (tid & 1) * 16;

    const __half* Abase = X  + (size_t)(row0 + lrow) * D_ + loff;
    const __half* Bbase = WT + (size_t)(col0 + lrow) * D_ + loff;

    auto load_stage = [&](int s, int k0) {
        cp16(&As[s][lrow][loff],     Abase + k0);
        cp16(&As[s][lrow][loff + 8], Abase + k0 + 8);
        cp16(&Bs[s][lrow][loff],     Bbase + k0);
        cp16(&Bs[s][lrow][loff + 8], Bbase + k0 + 8);
        cp_commit();
    };

    load_stage(0, 0);
    load_stage(1, 32);

    float acc[4][4][4];
    #pragma unroll
    for (int mt = 0; mt < 4; mt++)
        #pragma unroll
        for (int nt = 0; nt < 4; nt++)
            #pragma unroll
            for (int i = 0; i < 4; i++) acc[mt][nt][i] = 0.f;

    // ldmatrix lane addressing
    const int a_r = lane & 15;
    const int a_c = ((lane >> 4) & 1) * 8;
    const int b_r = ((lane >> 4) & 1) * 8 + (lane & 7);
    const int b_c = ((lane >> 3) & 1) * 8;

    const int NIT = D_ / 32;
    for (int it = 0; it < NIT; it++) {
        cp_wait1();
        __syncthreads();
        const int s = it & 1;

        #pragma unroll
        for (int ks = 0; ks < 2; ks++) {
            const int kb = ks * 16;
            uint32_t af[4][4];
            #pragma unroll
            for (int mt = 0; mt < 4; mt++)
                ldsm4(af[mt], &As[s][warp_m*64 + mt*16 + a_r][kb + a_c]);
            uint32_t bf[4][2];
            #pragma unroll
            for (int ntp = 0; ntp < 2; ntp++) {
                uint32_t t[4];
                ldsm4(t, &Bs[s][warp_n*32 + ntp*16 + b_r][kb + b_c]);
                bf[2*ntp][0]   = t[0]; bf[2*ntp][1]   = t[1];
                bf[2*ntp+1][0] = t[2]; bf[2*ntp+1][1] = t[3];
            }
            #pragma unroll
            for (int mt = 0; mt < 4; mt++)
                #pragma unroll
                for (int nt = 0; nt < 4; nt++)
                    mma_f16(acc[mt][nt], af[mt], bf[nt]);
        }
        __syncthreads();
        const int knext = (it + 2 < NIT) ? (it + 2) * 32 : 0;
        load_stage(s, knext);
    }

    #pragma unroll
    for (int nt = 0; nt < 4; nt++) {
        const int c  = col0 + warp_n * 32 + nt * 8 + tg * 2;
        const float bx = bias[c];
        const float by = bias[c + 1];
        #pragma unroll
        for (int mt = 0; mt < 4; mt++) {
            const int r = row0 + warp_m * 64 + mt * 16 + g;
            if (MODE == 0) {
                __half* oh = (__half*)outp;
                __half2 v0 = __floats2half2_rn(acc[mt][nt][0] + bx, acc[mt][nt][1] + by);
                __half2 v1 = __floats2half2_rn(acc[mt][nt][2] + bx, acc[mt][nt][3] + by);
                const int h = c >> 6, d = c & 63;
                const int b0 = r >> 10,       s0 = r & (S_ - 1);
                const int b1 = (r + 8) >> 10, s1 = (r + 8) & (S_ - 1);
                *(__half2*)(&oh[(((size_t)(b0 * H_ + h)) * S_ + s0) * HD_ + d]) = v0;
                *(__half2*)(&oh[(((size_t)(b1 * H_ + h)) * S_ + s1) * HD_ + d]) = v1;
            } else {
                float* of = (float*)outp;
                float2 v0 = make_float2(acc[mt][nt][0] + bx, acc[mt][nt][1] + by);
                float2 v1 = make_float2(acc[mt][nt][2] + bx, acc[mt][nt][3] + by);
                *(float2*)(&of[(size_t)r * D_ + c])       = v0;
                *(float2*)(&of[(size_t)(r + 8) * D_ + c]) = v1;
            }
        }
    }
}

__global__ __launch_bounds__(256, 2) void qkv_proj_kernel(
    const float* __restrict__ bq, const float* __restrict__ bk,
    const float* __restrict__ bv)
{
    const int z = blockIdx.z;
    const float* bias = (z == 0) ? bq : (z == 1) ? bk : bv;
    __half* outp = (z == 0) ? g_Qh : (z == 1) ? g_Kh : g_Vh;
    gemm_f16_body<0>(g_Xh[z], g_WT[z], bias, outp);
}

__global__ __launch_bounds__(256, 2) void out_proj_kernel(const float* __restrict__ bo)
{
    gemm_f16_body<1>(g_attn_h, g_WT[3], bo, g_proj);
}

// ============================================================
// Flash attention (causal), fp16 tensor cores.
// 256 threads = 8 warps; CTA = 128 q-rows; warp owns 16 rows.
// KV tile 64x64 per j-iteration. P stays in registers.
// ============================================================
__global__ __launch_bounds__(256, 2) void attn_kernel(const int* __restrict__ mask)
{
    __shared__ __align__(16) __half Ks[64][72];   // [col n][k d]
    __shared__ __align__(16) __half Vs[64][72];   // [k][d]
    __shared__ float Ms[64];

    const int qt = (int)gridDim.x - 1 - (int)blockIdx.x;  // heavy tiles first
    const int bh = blockIdx.y;
    const int b  = bh >> 4;
    const int h  = bh & 15;

    const int tid  = threadIdx.x;
    const int wid  = tid >> 5;
    const int lane = tid & 31;
    const int g    = lane >> 2;
    const int tg   = lane & 3;
    const int m0   = wid * 16;       // 0..112

    const __half* __restrict__ Qg = g_Qh + (size_t)bh * S_ * HD_;
    const __half* __restrict__ Kg = g_Kh + (size_t)bh * S_ * HD_;
    const __half* __restrict__ Vg = g_Vh + (size_t)bh * S_ * HD_;

    // ---- stage this warp's 16 Q rows into smem (warps 0-3 -> Ks, 4-7 -> Vs)
    __half (*Qst)[72] = (wid < 4) ? Ks : Vs;
    const int sr0 = (wid & 3) * 16;
    {
        const int r   = lane >> 1;          // 0..15
        const int off = (lane & 1) * 32;
        const __half* Qrow = Qg + (size_t)(qt*128 + m0 + r) * HD_ + off;
        *(uint4*)(&Qst[sr0 + r][off])      = *(const uint4*)(Qrow);
        *(uint4*)(&Qst[sr0 + r][off + 8])  = *(const uint4*)(Qrow + 8);
        *(uint4*)(&Qst[sr0 + r][off + 16]) = *(const uint4*)(Qrow + 16);
        *(uint4*)(&Qst[sr0 + r][off + 24]) = *(const uint4*)(Qrow + 24);
    }
    __syncwarp();

    const int a_r = lane & 15;
    const int a_c = ((lane >> 4) & 1) * 8;
    const int b_r = ((lane >> 4) & 1) * 8 + (lane & 7);
    const int b_c = ((lane >> 3) & 1) * 8;
    const int vrow_off = ((lane >> 3) & 1) * 8 + (lane & 7);
    const int vcol_off = ((lane >> 4) & 1) * 8;

    uint32_t qf[4][4];
    #pragma unroll
    for (int ks = 0; ks < 4; ks++)
        ldsm4(qf[ks], &Qst[sr0 + a_r][ks*16 + a_c]);

    float m_i[2] = {-1e30f, -1e30f};
    float l_i[2] = {0.f, 0.f};
    float o[8][4];
    #pragma unroll
    for (int dt = 0; dt < 8; dt++)
        #pragma unroll
        for (int i = 0; i < 4; i++) o[dt][i] = 0.f;

    const int qr0 = qt*128 + m0 + g;

    const int fr = tid >> 2;            // 0..63
    const int fc = (tid & 3) * 16;      // 0,16,32,48 halfs

    const int jmax = 2*qt + 1;
    for (int j = 0; j <= jmax; j++) {
        __syncthreads();   // everyone done with Ks/Vs (incl. Q staging on iter 0)
        {
            const __half* Krow = Kg + (size_t)(j*64 + fr) * HD_ + fc;
            const __half* Vrow = Vg + (size_t)(j*64 + fr) * HD_ + fc;
            *(uint4*)(&Ks[fr][fc])     = *(const uint4*)(Krow);
            *(uint4*)(&Ks[fr][fc + 8]) = *(const uint4*)(Krow + 8);
            *(uint4*)(&Vs[fr][fc])     = *(const uint4*)(Vrow);
            *(uint4*)(&Vs[fr][fc + 8]) = *(const uint4*)(Vrow + 8);
        }
        if (tid < 64)
            Ms[tid] = (mask[b*S_ + j*64 + tid] == 0) ? -1e9f : 0.f;
        __syncthreads();

        // ---- S = Q K^T (16x64 per warp), K frags via ldmatrix
        float s[8][4];
        #pragma unroll
        for (int nt = 0; nt < 8; nt++)
            #pragma unroll
            for (int i = 0; i < 4; i++) s[nt][i] = 0.f;

        #pragma unroll
        for (int ks = 0; ks < 4; ks++) {
            const int kb = ks * 16;
            #pragma unroll
            for (int ntp = 0; ntp < 4; ntp++) {
                uint32_t t[4];
                ldsm4(t, &Ks[ntp*16 + b_r][kb + b_c]);
                uint32_t bfa[2] = {t[0], t[1]};
                uint32_t bfb[2] = {t[2], t[3]};
                mma_f16(s[2*ntp],     qf[ks], bfa);
                mma_f16(s[2*ntp + 1], qf[ks], bfb);
            }
        }

        // ---- scale + mask
        const bool diag = (j*64 + 63) > (qt*128 + m0);
        #pragma unroll
        for (int nt = 0; nt < 8; nt++) {
            const int c0 = nt*8 + 2*tg;
            const float ma = Ms[c0];
            const float mb = Ms[c0 + 1];
            s[nt][0] = s[nt][0] * 0.125f + ma;
            s[nt][1] = s[nt][1] * 0.125f + mb;
            s[nt][2] = s[nt][2] * 0.125f + ma;
            s[nt][3] = s[nt][3] * 0.125f + mb;
            if (diag) {
                const int gc0 = j*64 + c0;
                if (gc0 > qr0)         s[nt][0] = -1e9f;
                if (gc0 + 1 > qr0)     s[nt][1] = -1e9f;
                if (gc0 > qr0 + 8)     s[nt][2] = -1e9f;
                if (gc0 + 1 > qr0 + 8) s[nt][3] = -1e9f;
            }
        }

        // ---- online softmax (rows g, g+8)
        float rm0 = -1e30f, rm1 = -1e30f;
        #pragma unroll
        for (int nt = 0; nt < 8; nt++) {
            rm0 = fmaxf(rm0, fmaxf(s[nt][0], s[nt][1]));
            rm1 = fmaxf(rm1, fmaxf(s[nt][2], s[nt][3]));
        }
        rm0 = fmaxf(rm0, __shfl_xor_sync(0xffffffffu, rm0, 1));
        rm0 = fmaxf(rm0, __shfl_xor_sync(0xffffffffu, rm0, 2));
        rm1 = fmaxf(rm1, __shfl_xor_sync(0xffffffffu, rm1, 1));
        rm1 = fmaxf(rm1, __shfl_xor_sync(0xffffffffu, rm1, 2));

        const float mn0 = fmaxf(m_i[0], rm0);
        const float mn1 = fmaxf(m_i[1], rm1);
        const float corr0 = __expf(m_i[0] - mn0);
        const float corr1 = __expf(m_i[1] - mn1);
        m_i[0] = mn0; m_i[1] = mn1;

        float rs0 = 0.f, rs1 = 0.f;
        #pragma unroll
        for (int nt = 0; nt < 8; nt++) {
            s[nt][0] = __expf(s[nt][0] - mn0);
            s[nt][1] = __expf(s[nt][1] - mn0);
            s[nt][2] = __expf(s[nt][2] - mn1);
            s[nt][3] = __expf(s[nt][3] - mn1);
            rs0 += s[nt][0] + s[nt][1];
            rs1 += s[nt][2] + s[nt][3];
        }
        rs0 += __shfl_xor_sync(0xffffffffu, rs0, 1);
        rs0 += __shfl_xor_sync(0xffffffffu, rs0, 2);
        rs1 += __shfl_xor_sync(0xffffffffu, rs1, 1);
        rs1 += __shfl_xor_sync(0xffffffffu, rs1, 2);
        l_i[0] = l_i[0] * corr0 + rs0;
        l_i[1] = l_i[1] * corr1 + rs1;

        #pragma unroll
        for (int dt = 0; dt < 8; dt++) {
            o[dt][0] *= corr0; o[dt][1] *= corr0;
            o[dt][2] *= corr1; o[dt][3] *= corr1;
        }

        // ---- O += P @ V : P fragments straight from registers
        #pragma unroll
        for (int ks = 0; ks < 4; ks++) {
            uint32_t af[4];
            af[0] = packh2(s[2*ks][0],     s[2*ks][1]);
            af[1] = packh2(s[2*ks][2],     s[2*ks][3]);
            af[2] = packh2(s[2*ks + 1][0], s[2*ks + 1][1]);
            af[3] = packh2(s[2*ks + 1][2], s[2*ks + 1][3]);
            #pragma unroll
            for (int dt2 = 0; dt2 < 4; dt2++) {
                uint32_t t[4];
                ldsm4t(t, &Vs[ks*16 + vrow_off][dt2*16 + vcol_off]);
                uint32_t bfa[2] = {t[0], t[1]};
                uint32_t bfb[2] = {t[2], t[3]};
                mma_f16(o[dt2*2],     af, bfa);
                mma_f16(o[dt2*2 + 1], af, bfb);
            }
        }
    }

    // ---- normalize + write half [B,S,D]
    const float inv0 = 1.f / l_i[0];
    const float inv1 = 1.f / l_i[1];
    #pragma unroll
    for (int dt = 0; dt < 8; dt++) {
        const int c = h*64 + dt*8 + 2*tg;
        *(__half2*)(&g_attn_h[((size_t)(b*S_ + qr0))*D_ + c]) =
            __floats2half2_rn(o[dt][0] * inv0, o[dt][1] * inv0);
        *(__half2*)(&g_attn_h[((size_t)(b*S_ + qr0 + 8))*D_ + c]) =
            __floats2half2_rn(o[dt][2] * inv1, o[dt][3] * inv1);
    }
}

// ============================================================
// Residual add + LayerNorm (unbiased var /1023, eps added to std)
// ============================================================
__global__ __launch_bounds__(256) void ln_kernel(
    const float* __restrict__ query,
    const float* __restrict__ lw, const float* __restrict__ lb,
    float* __restrict__ out)
{
    __shared__ float xs[D_];
    __shared__ float red[8];
    const int r   = blockIdx.x;
    const int tid = threadIdx.x;
    const size_t base = (size_t)r * D_;

    float s = 0.f;
    #pragma unroll
    for (int i = tid; i < D_; i += 256) {
        float v = g_proj[base + i] + query[base + i];
        xs[i] = v;
        s += v;
    }
    #pragma unroll
    for (int off = 16; off >= 1; off >>= 1) s += __shfl_xor_sync(~0u, s, off);
    if ((tid & 31) == 0) red[tid >> 5] = s;
    __syncthreads();
    if (tid < 32) {
        float t = (tid < 8) ? red[tid] : 0.f;
        #pragma unroll
        for (int off = 4; off >= 1; off >>= 1) t += __shfl_xor_sync(~0u, t, off);
        if (tid == 0) red[0] = t;
    }
    __syncthreads();
    const float mean = red[0] * (1.f / (float)D_);
    __syncthreads();

    float sv = 0.f;
    #pragma unroll
    for (int i = tid; i < D_; i += 256) {
        float d = xs[i] - mean;
        sv += d * d;
    }
    #pragma unroll
    for (int off = 16; off >= 1; off >>= 1) sv += __shfl_xor_sync(~0u, sv, off);
    if ((tid & 31) == 0) red[tid >> 5] = sv;
    __syncthreads();
    if (tid < 32) {
        float t = (tid < 8) ? red[tid] : 0.f;
        #pragma unroll
        for (int off = 4; off >= 1; off >>= 1) t += __shfl_xor_sync(~0u, t, off);
        if (tid == 0) red[0] = t;
    }
    __syncthreads();
    const float var = red[0] * (1.f / (float)(D_ - 1));
    const float inv = 1.f / (sqrtf(var) + 1e-6f);

    #pragma unroll
    for (int i = tid; i < D_; i += 256)
        out[base + i] = lw[i] * (xs[i] - mean) * inv + lb[i];
}

// ============================================================
extern "C" void kernel_launch(void* const* d_in, const int* in_sizes, int n_in,
                              void* d_out, int out_size)
{
    const float* query = (const float*)d_in[0];
    const float* key   = (const float*)d_in[1];
    const float* value = (const float*)d_in[2];
    const int*   mask  = (const int*)  d_in[3];
    const float* Wq    = (const float*)d_in[4];
    const float* bq    = (const float*)d_in[5];
    const float* Wk    = (const float*)d_in[6];
    const float* bk    = (const float*)d_in[7];
    const float* Wv    = (const float*)d_in[8];
    const float* bv    = (const float*)d_in[9];
    const float* Wo    = (const float*)d_in[10];
    const float* bo    = (const float*)d_in[11];
    const float* ln_w  = (const float*)d_in[12];
    const float* ln_b  = (const float*)d_in[13];
    float* out = (float*)d_out;

    conv_in_kernel<<<dim3(MTOT*D_/1024, 3), 256>>>(query, key, value);
    conv_w_kernel<<<dim3(32, 32, 4), 256>>>(Wq, Wk, Wv, Wo);
    qkv_proj_kernel<<<dim3(8, 32, 3), 256>>>(bq, bk, bv);
    attn_kernel<<<dim3(8, 64), 256>>>(mask);
    out_proj_kernel<<<dim3(8, 32), 256>>>(bo);
    ln_kernel<<<B_*S_, 256>>>(query, ln_w, ln_b, out);
}